// round 9
// baseline (speedup 1.0000x reference)
#include <cuda_runtime.h>
#include <cuda_fp16.h>
#include <math.h>
#include <stdint.h>

#define EMBED 768
#define HEADS 12
#define HDIM  64
#define FF    1536
#define BATCH 4
#define LQ    2048
#define LK    2048
#define MQ    (BATCH*LQ)   /* 8192 */
#define MK    (BATCH*LK)   /* 8192 */
#define WSZ   (EMBED*EMBED)
#define WFSZ  (EMBED*FF)

// ---------------- scratch (no allocations allowed) ----------------
__device__ float  g_qp [MQ*EMBED];
__device__ float  g_kp [MK*EMBED];
__device__ float  g_vp [MK*EMBED];
__device__ float  g_o  [MQ*EMBED];
__device__ float  g_ln1[MQ*EMBED];
__device__ float  g_f2 [MQ*EMBED];
__device__ __half g_hit[MQ*EMBED];      // image_tokens fp16
__device__ __half g_hip[MQ*EMBED];      // image_pos fp16
__device__ __half g_hpp[MK*EMBED];      // point_pos fp16
__device__ __half g_hpt[MK*EMBED];      // point_tokens fp16
__device__ __half g_qh [MQ*EMBED];
__device__ __half g_kh [MK*EMBED];
__device__ __half g_vt [BATCH*EMBED*LK];
__device__ __half g_hat[MQ*EMBED];
__device__ __half g_hln[MQ*EMBED];
__device__ __half g_hff[MQ*FF];
__device__ __half g_wh [6*WSZ + 2*WFSZ]; // transposed fp16 weights Wt[n][k]
__device__ __half g_wf [2*WSZ];          // fused transposed weights (Wip@Wq)^T, (Wpp@Wk)^T
__device__ float  g_bf [2*EMBED];        // fused biases

// ---------------- helpers ----------------
__device__ __forceinline__ void cpasync16(void* s, const void* g) {
    uint32_t sa = (uint32_t)__cvta_generic_to_shared(s);
    asm volatile("cp.async.cg.shared.global [%0], [%1], 16;" :: "r"(sa), "l"(g));
}
#define CP_COMMIT() asm volatile("cp.async.commit_group;")

__device__ __forceinline__ uint32_t smem_u32(const void* p) {
    return (uint32_t)__cvta_generic_to_shared(p);
}

__device__ __forceinline__ void mma_f16(float c[4], const uint32_t a[4], const uint32_t b[2])
{
    asm volatile(
        "mma.sync.aligned.m16n8k16.row.col.f32.f16.f16.f32 "
        "{%0,%1,%2,%3}, {%4,%5,%6,%7}, {%8,%9}, {%0,%1,%2,%3};"
        : "+f"(c[0]), "+f"(c[1]), "+f"(c[2]), "+f"(c[3])
        : "r"(a[0]), "r"(a[1]), "r"(a[2]), "r"(a[3]), "r"(b[0]), "r"(b[1]));
}

__device__ __forceinline__ void ldsm_x4(uint32_t r[4], uint32_t addr) {
    asm volatile("ldmatrix.sync.aligned.m8n8.x4.shared.b16 {%0,%1,%2,%3}, [%4];"
        : "=r"(r[0]), "=r"(r[1]), "=r"(r[2]), "=r"(r[3]) : "r"(addr));
}

// ---------------- prep: fp16 copies of the four A-side inputs ----------------
__global__ void cvt4(const float* __restrict__ a, const float* __restrict__ b,
                     const float* __restrict__ c, const float* __restrict__ d,
                     __half* __restrict__ ha, __half* __restrict__ hb,
                     __half* __restrict__ hc, __half* __restrict__ hd)
{
    size_t i = ((size_t)blockIdx.x * 256 + threadIdx.x) * 4;
    if (i >= (size_t)MQ*EMBED) return;
    float4 va = *(const float4*)(a + i);
    float4 vb = *(const float4*)(b + i);
    float4 vc = *(const float4*)(c + i);
    float4 vd = *(const float4*)(d + i);
    *(__half2*)(ha + i)     = __floats2half2_rn(va.x, va.y);
    *(__half2*)(ha + i + 2) = __floats2half2_rn(va.z, va.w);
    *(__half2*)(hb + i)     = __floats2half2_rn(vb.x, vb.y);
    *(__half2*)(hb + i + 2) = __floats2half2_rn(vb.z, vb.w);
    *(__half2*)(hc + i)     = __floats2half2_rn(vc.x, vc.y);
    *(__half2*)(hc + i + 2) = __floats2half2_rn(vc.z, vc.w);
    *(__half2*)(hd + i)     = __floats2half2_rn(vd.x, vd.y);
    *(__half2*)(hd + i + 2) = __floats2half2_rn(vd.z, vd.w);
}

// ---------------- weight transpose + fp16 convert ----------------
struct WPtrs { const float* s[8]; };

__global__ void twr_all(WPtrs P, __half* __restrict__ wh)
{
    const int z = blockIdx.z;
    const int K = (z == 7) ? FF : EMBED;
    const int N = (z == 6) ? FF : EMBED;
    const int n0 = blockIdx.x * 32, k0 = blockIdx.y * 32;
    if (n0 >= N || k0 >= K) return;
    const float* src = P.s[z];
    size_t off = (z <= 5) ? (size_t)z * WSZ : (z == 6 ? (size_t)6*WSZ : (size_t)6*WSZ + WFSZ);
    __half* dst = wh + off;

    __shared__ float t[32][33];
    #pragma unroll
    for (int i = 0; i < 32; i += 8)
        t[threadIdx.y + i][threadIdx.x] =
            src[(size_t)(k0 + threadIdx.y + i) * N + n0 + threadIdx.x];
    __syncthreads();
    #pragma unroll
    for (int i = 0; i < 32; i += 8)
        dst[(size_t)(n0 + threadIdx.y + i) * K + k0 + threadIdx.x] =
            __float2half(t[threadIdx.x][threadIdx.y + i]);
}

// ---------------- fused weight product: wf[z][n][a] = sum_b Wpos[a][b] * Wproj[b][n] ----------------
__global__ void wfuse(const float* __restrict__ Wip, const float* __restrict__ Wq,
                      const float* __restrict__ Wpp, const float* __restrict__ Wk,
                      __half* __restrict__ wf)
{
    const int z  = blockIdx.z;
    const float* Wpos  = z ? Wpp : Wip;
    const float* Wproj = z ? Wk  : Wq;
    __half* dst = wf + (size_t)z * WSZ;
    const int a0 = blockIdx.x * 32;
    const int n0 = blockIdx.y * 32;
    const int tx = threadIdx.x, ty = threadIdx.y;   // (32, 8)

    __shared__ float Sq[32][33];   // Wproj[b][n]
    __shared__ float Sp[32][33];   // Wpos[a][b]
    float acc[4] = {0.f, 0.f, 0.f, 0.f};

    for (int b0 = 0; b0 < EMBED; b0 += 32) {
        #pragma unroll
        for (int i = 0; i < 32; i += 8) {
            Sq[ty + i][tx] = Wproj[(size_t)(b0 + ty + i) * EMBED + n0 + tx];
            Sp[ty + i][tx] = Wpos [(size_t)(a0 + ty + i) * EMBED + b0 + tx];
        }
        __syncthreads();
        #pragma unroll
        for (int bb = 0; bb < 32; bb++) {
            float pv = Sp[tx][bb];
            #pragma unroll
            for (int i = 0; i < 4; i++)
                acc[i] += Sq[bb][ty + 8*i] * pv;
        }
        __syncthreads();
    }
    #pragma unroll
    for (int i = 0; i < 4; i++)
        dst[(size_t)(n0 + ty + 8*i) * EMBED + a0 + tx] = __float2half(acc[i]);
}

// ---------------- fused bias: bf[z][n] = sum_j bsrc[j]*Wproj[j][n] + b0[n] ----------------
__global__ void bfuse(const float* __restrict__ bip, const float* __restrict__ bq,
                      const float* __restrict__ Wq,
                      const float* __restrict__ bpp, const float* __restrict__ bk,
                      const float* __restrict__ Wk,
                      float* __restrict__ bf)
{
    const int z = blockIdx.y;
    const float* bsrc = z ? bpp : bip;
    const float* b0   = z ? bk  : bq;
    const float* W    = z ? Wk  : Wq;
    const int n = blockIdx.x * 256 + threadIdx.x;
    float acc = b0[n];
    for (int j = 0; j < EMBED; j++)
        acc += bsrc[j] * W[(size_t)j * EMBED + n];
    bf[z*EMBED + n] = acc;
}

// ---------------- fp16 GEMM 128x128, K-stage 64, ldmatrix + 3-stage cp.async ----------------
// Optional second phase (A2, Wt2, K2) accumulates into the same tile (concat-K fusion).
// EPI bit0 = +residual R (fp32), bit1 = exact GELU, bit3 = fp16 output
#define HG_STAGE 36864
#define HG_SMEM  (3 * HG_STAGE)   /* 110592 */

template<int EPI>
__global__ __launch_bounds__(256, 2)
void hgemm(const __half* __restrict__ A, const __half* __restrict__ Wt,
           const __half* __restrict__ A2, const __half* __restrict__ Wt2, int K2,
           const float* __restrict__ bias, const float* __restrict__ R,
           void* __restrict__ Cv, int M, int N, int K)
{
    extern __shared__ char smem[];

    const int tid  = threadIdx.x;
    const int lane = tid & 31;
    const int warp = tid >> 5;
    const int wm   = warp & 3;
    const int wn   = warp >> 2;
    const int bm   = blockIdx.y * 128;
    const int bn   = blockIdx.x * 128;

    float acc[2][8][4];
    #pragma unroll
    for (int mi = 0; mi < 2; mi++)
        #pragma unroll
        for (int ni = 0; ni < 8; ni++)
            #pragma unroll
            for (int t = 0; t < 4; t++) acc[mi][ni][t] = 0.f;

    const int g  = lane >> 3;
    const int ri = lane & 7;
    const int rowA_off = (wm*32 + (g & 1)*8 + ri) * 144 + (g >> 1)*16;
    const int rowB_off = 18432 + (wn*64 + (g >> 1)*8 + ri) * 144 + (g & 1)*16;

    const __half* Ap = A;
    const __half* Wp = Wt;
    int Kp = K;

    #define HG_PREFETCH(s)  do {                                                     \
        char* _b = smem + ((s) % 3) * HG_STAGE;                                      \
        const int _k0 = (s) * 64;                                                    \
        _Pragma("unroll")                                                            \
        for (int _i = 0; _i < 4; _i++) {                                             \
            int _id = tid + 256*_i;                                                  \
            int _r = _id >> 3, _c = _id & 7;                                         \
            cpasync16(_b + _r*144 + _c*16,         Ap + (size_t)(bm + _r) * Kp + _k0 + _c*8); \
            cpasync16(_b + 18432 + _r*144 + _c*16, Wp + (size_t)(bn + _r) * Kp + _k0 + _c*8); \
        }                                                                            \
        CP_COMMIT();                                                                 \
    } while (0)

    for (int ph = 0; ph < 2; ph++) {
        const int NT = Kp / 64;
        HG_PREFETCH(0);
        HG_PREFETCH(1);
        for (int s = 0; s < NT; s++) {
            if (s + 1 < NT) { asm volatile("cp.async.wait_group 1;"); }
            else            { asm volatile("cp.async.wait_group 0;"); }
            __syncthreads();
            if (s + 2 < NT) HG_PREFETCH(s + 2);

            const uint32_t buf = smem_u32(smem + (s % 3) * HG_STAGE);
            #pragma unroll
            for (int kk = 0; kk < 4; kk++) {
                uint32_t a[2][4];
                #pragma unroll
                for (int mi = 0; mi < 2; mi++)
                    ldsm_x4(a[mi], buf + rowA_off + mi*16*144 + kk*32);
                uint32_t b4[4][4];
                #pragma unroll
                for (int p = 0; p < 4; p++)
                    ldsm_x4(b4[p], buf + rowB_off + p*16*144 + kk*32);
                #pragma unroll
                for (int mi = 0; mi < 2; mi++)
                    #pragma unroll
                    for (int ni = 0; ni < 8; ni++)
                        mma_f16(acc[mi][ni], a[mi], &b4[ni >> 1][(ni & 1)*2]);
            }
        }
        if (!A2 || ph == 1) break;
        __syncthreads();
        Ap = A2; Wp = Wt2; Kp = K2;
    }
    #undef HG_PREFETCH

    // epilogue
    #pragma unroll
    for (int mi = 0; mi < 2; mi++) {
        const int r0 = bm + wm*32 + mi*16 + (lane>>2);
        #pragma unroll
        for (int ni = 0; ni < 8; ni++) {
            const int c = bn + wn*64 + ni*8 + 2*(lane & 3);
            const float2 bb = *(const float2*)(bias + c);
            #pragma unroll
            for (int half_ = 0; half_ < 2; half_++) {
                const int r = r0 + half_*8;
                float v0 = acc[mi][ni][2*half_+0] + bb.x;
                float v1 = acc[mi][ni][2*half_+1] + bb.y;
                if (EPI & 1) {
                    const float2 rr = *(const float2*)(R + (size_t)r * N + c);
                    v0 += rr.x; v1 += rr.y;
                }
                if (EPI & 2) {
                    v0 = 0.5f * v0 * (1.f + erff(v0 * 0.70710678118654752f));
                    v1 = 0.5f * v1 * (1.f + erff(v1 * 0.70710678118654752f));
                }
                if (EPI & 8)
                    *(__half2*)((__half*)Cv + (size_t)r * N + c) = __floats2half2_rn(v0, v1);
                else
                    *(float2*)((float*)Cv + (size_t)r * N + c) = make_float2(v0, v1);
            }
        }
    }
}

// ---------------- per-head L2 normalize: fp32 in -> fp16 out ----------------
__global__ void l2norm_kernel(const float* __restrict__ x, __half* __restrict__ y, int nvec)
{
    const int warp = (blockIdx.x * blockDim.x + threadIdx.x) >> 5;
    const int lane = threadIdx.x & 31;
    if (warp >= nvec) return;
    const float* p = x + (size_t)warp * HDIM;
    float a = p[lane], b = p[lane + 32];
    float ss = a*a + b*b;
    #pragma unroll
    for (int m = 16; m; m >>= 1) ss += __shfl_xor_sync(0xffffffffu, ss, m);
    float n   = sqrtf(ss);
    float inv = 1.f / fmaxf(n, 1e-12f);
    __half* q = y + (size_t)warp * HDIM;
    q[lane]      = __float2half(a * inv);
    q[lane + 32] = __float2half(b * inv);
}

// ---------------- V transpose ----------------
__global__ void vtrans_kernel(const float* __restrict__ vp, __half* __restrict__ vt)
{
    const int t0 = blockIdx.x * 32;
    const int d0 = blockIdx.y * 32;
    const int b  = blockIdx.z;
    __shared__ float t[32][33];
    #pragma unroll
    for (int i = 0; i < 32; i += 8)
        t[threadIdx.y + i][threadIdx.x] =
            vp[(size_t)(b*LK + t0 + threadIdx.y + i) * EMBED + d0 + threadIdx.x];
    __syncthreads();
    #pragma unroll
    for (int i = 0; i < 32; i += 8)
        vt[(size_t)(b*EMBED + d0 + threadIdx.y + i) * LK + t0 + threadIdx.x] =
            __float2half(t[threadIdx.x][threadIdx.y + i]);
}

// ---------------- LayerNorm over 768 ----------------
template<bool DUAL>
__global__ void layernorm_kernel(const float* __restrict__ x,
                                 const float* __restrict__ g,
                                 const float* __restrict__ b,
                                 float* __restrict__ y, __half* __restrict__ yh)
{
    const int row = blockIdx.x;
    const float* xr = x + (size_t)row * EMBED;
    const int tid = threadIdx.x;

    float v0 = xr[tid], v1 = xr[tid + 256], v2 = xr[tid + 512];

    __shared__ float red[8];
    float s = v0 + v1 + v2;
    #pragma unroll
    for (int m = 16; m; m >>= 1) s += __shfl_xor_sync(0xffffffffu, s, m);
    if ((tid & 31) == 0) red[tid >> 5] = s;
    __syncthreads();
    s = 0.f;
    #pragma unroll
    for (int w = 0; w < 8; w++) s += red[w];
    const float mu = s * (1.f / EMBED);
    __syncthreads();

    float d0 = v0 - mu, d1 = v1 - mu, d2 = v2 - mu;
    float ss = d0*d0 + d1*d1 + d2*d2;
    #pragma unroll
    for (int m = 16; m; m >>= 1) ss += __shfl_xor_sync(0xffffffffu, ss, m);
    if ((tid & 31) == 0) red[tid >> 5] = ss;
    __syncthreads();
    ss = 0.f;
    #pragma unroll
    for (int w = 0; w < 8; w++) ss += red[w];
    const float inv = rsqrtf(ss * (1.f / EMBED) + 1e-5f);

    float o0 = d0 * inv * g[tid]       + b[tid];
    float o1 = d1 * inv * g[tid + 256] + b[tid + 256];
    float o2 = d2 * inv * g[tid + 512] + b[tid + 512];
    float* yr = y + (size_t)row * EMBED;
    yr[tid] = o0; yr[tid + 256] = o1; yr[tid + 512] = o2;
    if (DUAL) {
        __half* hr = yh + (size_t)row * EMBED;
        hr[tid] = __float2half(o0);
        hr[tid + 256] = __float2half(o1);
        hr[tid + 512] = __float2half(o2);
    }
}

// ---------------- fp16 flash attention, ldmatrix frags ----------------
#define ATT_SMEM (7 * 64 * 72 * 2)

__global__ __launch_bounds__(128)
void attn_kernel(const __half* __restrict__ q, const __half* __restrict__ k,
                 const __half* __restrict__ vt, __half* __restrict__ out)
{
    extern __shared__ __half hsm[];
    __half* Qs    = hsm;
    __half* Ks[2] = { Qs + 64*72,      Qs + 2*64*72 };
    __half* Vs[2] = { Qs + 3*64*72,    Qs + 4*64*72 };
    __half* Ps    = Qs + 5*64*72;

    const int tid  = threadIdx.x;
    const int lane = tid & 31;
    const int warp = tid >> 5;
    const int q0 = blockIdx.x * 64;
    const int h  = blockIdx.y;
    const int b  = blockIdx.z;

    const __half* qb  = q  + ((size_t)(b*LQ + q0)) * EMBED + h * HDIM;
    const __half* kb  = k  + ((size_t)(b*LK))      * EMBED + h * HDIM;
    const __half* vtb = vt + ((size_t)(b*EMBED + h*HDIM)) * LK;

    const int rl = tid >> 3;
    const int cl = (tid & 7) * 8;

    #pragma unroll
    for (int i = 0; i < 4; i++) {
        int r = rl + 16*i;
        cpasync16(Qs + r*72 + cl, qb + (size_t)r * EMBED + cl);
    }
    #pragma unroll
    for (int i = 0; i < 4; i++) {
        int r = rl + 16*i;
        cpasync16(Ks[0] + r*72 + cl, kb  + (size_t)r * EMBED + cl);
        cpasync16(Vs[0] + r*72 + cl, vtb + (size_t)r * LK + cl);
    }
    CP_COMMIT();

    float o[8][4];
    #pragma unroll
    for (int ni = 0; ni < 8; ni++)
        #pragma unroll
        for (int t = 0; t < 4; t++) o[ni][t] = 0.f;
    float l0 = 0.f, l1 = 0.f;

    __half* Pw = Ps + warp*16*72;
    const int rql = lane >> 2;

    const int g2 = lane >> 3, ri = lane & 7;
    const uint32_t aQoff = (uint32_t)((warp*16 + (g2 & 1)*8 + ri) * 144 + (g2 >> 1)*16);
    const uint32_t aPoff = (uint32_t)(((g2 & 1)*8 + ri) * 144 + (g2 >> 1)*16);
    const uint32_t bOff  = (uint32_t)(((g2 >> 1)*8 + ri) * 144 + (g2 & 1)*16);
    const uint32_t qA  = smem_u32(Qs) + aQoff;
    const uint32_t pA  = smem_u32(Pw) + aPoff;

    for (int kt = 0; kt < LK/64; kt++) {
        asm volatile("cp.async.wait_group 0;");
        __syncthreads();

        const uint32_t kB = smem_u32(Ks[kt & 1]) + bOff;
        const uint32_t vB = smem_u32(Vs[kt & 1]) + bOff;

        if (kt + 1 < LK/64) {
            __half* ksn = Ks[(kt+1) & 1];
            __half* vsn = Vs[(kt+1) & 1];
            const __half* kp = kb  + (size_t)(kt+1) * 64 * EMBED;
            const __half* vp = vtb + (size_t)(kt+1) * 64;
            #pragma unroll
            for (int i = 0; i < 4; i++) {
                int r = rl + 16*i;
                cpasync16(ksn + r*72 + cl, kp + (size_t)r * EMBED + cl);
                cpasync16(vsn + r*72 + cl, vp + (size_t)r * LK + cl);
            }
            CP_COMMIT();
        }

        float s[8][4];
        #pragma unroll
        for (int ni = 0; ni < 8; ni++)
            #pragma unroll
            for (int t = 0; t < 4; t++) s[ni][t] = 0.f;

        #pragma unroll
        for (int kk = 0; kk < 4; kk++) {
            uint32_t a[4];
            ldsm_x4(a, qA + kk*32);
            uint32_t bf4[4][4];
            #pragma unroll
            for (int p = 0; p < 4; p++)
                ldsm_x4(bf4[p], kB + p*16*144 + kk*32);
            #pragma unroll
            for (int ni = 0; ni < 8; ni++)
                mma_f16(s[ni], a, &bf4[ni >> 1][(ni & 1)*2]);
        }

        #pragma unroll
        for (int ni = 0; ni < 8; ni++) {
            float p0 = __expf(s[ni][0] - 1.f);
            float p1 = __expf(s[ni][1] - 1.f);
            float p2 = __expf(s[ni][2] - 1.f);
            float p3 = __expf(s[ni][3] - 1.f);
            l0 += p0 + p1;
            l1 += p2 + p3;
            __half* pp = Pw + rql*72 + ni*8 + 2*(lane & 3);
            *(__half2*)pp          = __floats2half2_rn(p0, p1);
            *(__half2*)(pp + 8*72) = __floats2half2_rn(p2, p3);
        }
        __syncwarp();

        #pragma unroll
        for (int kk = 0; kk < 4; kk++) {
            uint32_t a[4];
            ldsm_x4(a, pA + kk*32);
            uint32_t bf4[4][4];
            #pragma unroll
            for (int p = 0; p < 4; p++)
                ldsm_x4(bf4[p], vB + p*16*144 + kk*32);
            #pragma unroll
            for (int ni = 0; ni < 8; ni++)
                mma_f16(o[ni], a, &bf4[ni >> 1][(ni & 1)*2]);
        }
    }

    l0 += __shfl_xor_sync(0xffffffffu, l0, 1);
    l0 += __shfl_xor_sync(0xffffffffu, l0, 2);
    l1 += __shfl_xor_sync(0xffffffffu, l1, 1);
    l1 += __shfl_xor_sync(0xffffffffu, l1, 2);
    const float inv0 = 1.f / l0, inv1 = 1.f / l1;

    const int r = b*LQ + q0 + warp*16 + rql;
    #pragma unroll
    for (int ni = 0; ni < 8; ni++) {
        const int c = h*HDIM + ni*8 + 2*(lane & 3);
        *(__half2*)(out + (size_t)r * EMBED + c)     = __floats2half2_rn(o[ni][0]*inv0, o[ni][1]*inv0);
        *(__half2*)(out + (size_t)(r+8) * EMBED + c) = __floats2half2_rn(o[ni][2]*inv1, o[ni][3]*inv1);
    }
}

// ---------------- launch ----------------
extern "C" void kernel_launch(void* const* d_in, const int* in_sizes, int n_in,
                              void* d_out, int out_size)
{
    const float* image_tokens = (const float*)d_in[0];
    const float* point_tokens = (const float*)d_in[1];
    const float* image_pos    = (const float*)d_in[2];
    const float* point_pos    = (const float*)d_in[3];
    const float* Wip = (const float*)d_in[4];   const float* bip = (const float*)d_in[5];
    const float* Wpp = (const float*)d_in[6];   const float* bpp = (const float*)d_in[7];
    const float* Wq  = (const float*)d_in[8];   const float* bq  = (const float*)d_in[9];
    const float* Wk  = (const float*)d_in[10];  const float* bk  = (const float*)d_in[11];
    const float* Wv  = (const float*)d_in[12];  const float* bv  = (const float*)d_in[13];
    const float* Wo  = (const float*)d_in[14];  const float* bo  = (const float*)d_in[15];
    const float* g1  = (const float*)d_in[16];  const float* b1  = (const float*)d_in[17];
    const float* g2  = (const float*)d_in[18];  const float* b2  = (const float*)d_in[19];
    const float* Wf1 = (const float*)d_in[20];  const float* bf1 = (const float*)d_in[21];
    const float* Wf2 = (const float*)d_in[22];  const float* bf2 = (const float*)d_in[23];
    float* out = (float*)d_out;

    float  *qp, *kp, *vp, *op, *ln1p, *f2p, *bfp;
    __half *hit, *hip, *hpp, *hpt, *qh, *kh, *vt, *hat, *hln, *hff, *wh, *wf;
    cudaGetSymbolAddress((void**)&qp,  g_qp);
    cudaGetSymbolAddress((void**)&kp,  g_kp);
    cudaGetSymbolAddress((void**)&vp,  g_vp);
    cudaGetSymbolAddress((void**)&op,  g_o);
    cudaGetSymbolAddress((void**)&ln1p,g_ln1);
    cudaGetSymbolAddress((void**)&f2p, g_f2);
    cudaGetSymbolAddress((void**)&hit, g_hit);
    cudaGetSymbolAddress((void**)&hip, g_hip);
    cudaGetSymbolAddress((void**)&hpp, g_hpp);
    cudaGetSymbolAddress((void**)&hpt, g_hpt);
    cudaGetSymbolAddress((void**)&qh,  g_qh);
    cudaGetSymbolAddress((void**)&kh,  g_kh);
    cudaGetSymbolAddress((void**)&vt,  g_vt);
    cudaGetSymbolAddress((void**)&hat, g_hat);
    cudaGetSymbolAddress((void**)&hln, g_hln);
    cudaGetSymbolAddress((void**)&hff, g_hff);
    cudaGetSymbolAddress((void**)&wh,  g_wh);
    cudaGetSymbolAddress((void**)&wf,  g_wf);
    cudaGetSymbolAddress((void**)&bfp, g_bf);

    __half* WqT  = wh + 2*WSZ;
    __half* WkT  = wh + 3*WSZ;
    __half* WvT  = wh + 4*WSZ;
    __half* WoT  = wh + 5*WSZ;
    __half* Wf1T = wh + 6*WSZ;
    __half* Wf2T = wh + 6*WSZ + WFSZ;
    __half* Wfq  = wf;              // (Wip@Wq)^T
    __half* Wfk  = wf + WSZ;        // (Wpp@Wk)^T

    static cudaStream_t s1 = nullptr, s2 = nullptr;
    static cudaEvent_t evA = nullptr, evB = nullptr, evC = nullptr, evK = nullptr, evV = nullptr;
    if (!s1) {
        cudaStreamCreateWithFlags(&s1, cudaStreamNonBlocking);
        cudaStreamCreateWithFlags(&s2, cudaStreamNonBlocking);
        cudaEventCreateWithFlags(&evA, cudaEventDisableTiming);
        cudaEventCreateWithFlags(&evB, cudaEventDisableTiming);
        cudaEventCreateWithFlags(&evC, cudaEventDisableTiming);
        cudaEventCreateWithFlags(&evK, cudaEventDisableTiming);
        cudaEventCreateWithFlags(&evV, cudaEventDisableTiming);
    }

    cudaFuncSetAttribute(hgemm<0>,  cudaFuncAttributeMaxDynamicSharedMemorySize, HG_SMEM);
    cudaFuncSetAttribute(hgemm<1>,  cudaFuncAttributeMaxDynamicSharedMemorySize, HG_SMEM);
    cudaFuncSetAttribute(hgemm<10>, cudaFuncAttributeMaxDynamicSharedMemorySize, HG_SMEM);
    cudaFuncSetAttribute(attn_kernel, cudaFuncAttributeMaxDynamicSharedMemorySize, ATT_SMEM);

    // ---- prep: everything forks from origin stream via evA (capture-legal) ----
    WPtrs P;
    P.s[0]=Wip; P.s[1]=Wpp; P.s[2]=Wq; P.s[3]=Wk; P.s[4]=Wv; P.s[5]=Wo; P.s[6]=Wf1; P.s[7]=Wf2;
    twr_all<<<dim3(48, 48, 8), dim3(32, 8)>>>(P, wh);
    cudaEventRecord(evA, 0);

    // s1: fork, then input conversion (feeds all branches)
    cudaStreamWaitEvent(s1, evA, 0);
    cvt4<<<(MQ*EMBED/4 + 255)/256, 256, 0, s1>>>(image_tokens, image_pos, point_pos, point_tokens,
                                                 hit, hip, hpp, hpt);
    cudaEventRecord(evB, s1);

    // s2: fork, then fused weight/bias products
    cudaStreamWaitEvent(s2, evA, 0);
    wfuse<<<dim3(24, 24, 2), dim3(32, 8), 0, s2>>>(Wip, Wq, Wpp, Wk, wf);
    bfuse<<<dim3(3, 2), 256, 0, s2>>>(bip, bq, Wq, bpp, bk, Wk, bfp);
    cudaEventRecord(evC, s2);

    // ---- branch Q (s0): fused dual-A GEMM -> l2norm ----
    cudaStreamWaitEvent(0, evB, 0);
    cudaStreamWaitEvent(0, evC, 0);
    hgemm<0><<<dim3(EMBED/128, MQ/128), 256, HG_SMEM>>>(hit, WqT, hip, Wfq, EMBED,
                                                        bfp, nullptr, qp, MQ, EMBED, EMBED);
    l2norm_kernel<<<(MQ*HEADS)/8, 256>>>(qp, qh, MQ*HEADS);

    // ---- branch K (s1): cvt4 already in program order; needs fused weights ----
    cudaStreamWaitEvent(s1, evC, 0);
    hgemm<0><<<dim3(EMBED/128, MK/128), 256, HG_SMEM, s1>>>(hpt, WkT, hpp, Wfk, EMBED,
                                                            bfp + EMBED, nullptr, kp, MK, EMBED, EMBED);
    l2norm_kernel<<<(MK*HEADS)/8, 256, 0, s1>>>(kp, kh, MK*HEADS);
    cudaEventRecord(evK, s1);

    // ---- branch V (s2): needs hpt from cvt4 (evB); WvT from twr_all (already after evA) ----
    cudaStreamWaitEvent(s2, evB, 0);
    hgemm<0><<<dim3(EMBED/128, MK/128), 256, HG_SMEM, s2>>>(hpt, WvT, nullptr, nullptr, 0,
                                                            bv, nullptr, vp, MK, EMBED, EMBED);
    vtrans_kernel<<<dim3(LK/32, EMBED/32, BATCH), dim3(32, 8), 0, s2>>>(vp, vt);
    cudaEventRecord(evV, s2);

    // ---- join, attention, tail (s0) ----
    cudaStreamWaitEvent(0, evK, 0);
    cudaStreamWaitEvent(0, evV, 0);
    attn_kernel<<<dim3(LQ/64, HEADS, BATCH), 128, ATT_SMEM>>>(qh, kh, vt, hat);
    hgemm<1><<<dim3(EMBED/128, MQ/128), 256, HG_SMEM>>>(hat, WoT, nullptr, nullptr, 0,
                                                        bo, image_tokens, op, MQ, EMBED, EMBED);
    layernorm_kernel<true><<<MQ, 256>>>(op, g1, b1, ln1p, hln);
    hgemm<10><<<dim3(FF/128, MQ/128), 256, HG_SMEM>>>(hln, Wf1T, nullptr, nullptr, 0,
                                                      bf1, nullptr, hff, MQ, FF, EMBED);
    hgemm<1><<<dim3(EMBED/128, MQ/128), 256, HG_SMEM>>>(hff, Wf2T, nullptr, nullptr, 0,
                                                        bf2, ln1p, f2p, MQ, EMBED, FF);
    layernorm_kernel<false><<<MQ, 256>>>(f2p, g2, b2, out, nullptr);
}

// round 10
// speedup vs baseline: 1.2967x; 1.2967x over previous
#include <cuda_runtime.h>
#include <cuda_fp16.h>
#include <math.h>
#include <stdint.h>

#define EMBED 768
#define HEADS 12
#define HDIM  64
#define FF    1536
#define BATCH 4
#define LQ    2048
#define LK    2048
#define MQ    (BATCH*LQ)   /* 8192 */
#define MK    (BATCH*LK)   /* 8192 */
#define WSZ   (EMBED*EMBED)
#define WFSZ  (EMBED*FF)

// ---------------- scratch (no allocations allowed) ----------------
__device__ float  g_o  [MQ*EMBED];
__device__ float  g_ln1[MQ*EMBED];
__device__ float  g_f2 [MQ*EMBED];
__device__ __half g_hA [MQ*EMBED];      // q-chain intermediate fp16
__device__ __half g_hB [MK*EMBED];      // k-chain intermediate fp16
__device__ __half g_hv [MK*EMBED];      // v projection fp16
__device__ __half g_hip[MQ*EMBED];      // image_pos fp16
__device__ __half g_hpp[MK*EMBED];      // point_pos fp16
__device__ __half g_hpt[MK*EMBED];      // point_tokens fp16
__device__ __half g_qh [MQ*EMBED];
__device__ __half g_kh [MK*EMBED];
__device__ __half g_vt [BATCH*EMBED*LK];
__device__ __half g_hat[MQ*EMBED];
__device__ __half g_hln[MQ*EMBED];
__device__ __half g_hff[MQ*FF];
__device__ __half g_wh [6*WSZ + 2*WFSZ]; // transposed fp16 weights Wt[n][k]

// ---------------- helpers ----------------
__device__ __forceinline__ void cpasync16(void* s, const void* g) {
    uint32_t sa = (uint32_t)__cvta_generic_to_shared(s);
    asm volatile("cp.async.cg.shared.global [%0], [%1], 16;" :: "r"(sa), "l"(g));
}
#define CP_COMMIT() asm volatile("cp.async.commit_group;")

__device__ __forceinline__ uint32_t smem_u32(const void* p) {
    return (uint32_t)__cvta_generic_to_shared(p);
}

__device__ __forceinline__ void mma_f16(float c[4], const uint32_t a[4], const uint32_t b[2])
{
    asm volatile(
        "mma.sync.aligned.m16n8k16.row.col.f32.f16.f16.f32 "
        "{%0,%1,%2,%3}, {%4,%5,%6,%7}, {%8,%9}, {%0,%1,%2,%3};"
        : "+f"(c[0]), "+f"(c[1]), "+f"(c[2]), "+f"(c[3])
        : "r"(a[0]), "r"(a[1]), "r"(a[2]), "r"(a[3]), "r"(b[0]), "r"(b[1]));
}

__device__ __forceinline__ void ldsm_x4(uint32_t r[4], uint32_t addr) {
    asm volatile("ldmatrix.sync.aligned.m8n8.x4.shared.b16 {%0,%1,%2,%3}, [%4];"
        : "=r"(r[0]), "=r"(r[1]), "=r"(r[2]), "=r"(r[3]) : "r"(addr));
}

// ---------------- prep: fp16 copies of the three A-side inputs ----------------
__global__ void cvt3(const float* __restrict__ a, const float* __restrict__ b,
                     const float* __restrict__ c, __half* __restrict__ ha,
                     __half* __restrict__ hb, __half* __restrict__ hc)
{
    size_t i = ((size_t)blockIdx.x * 256 + threadIdx.x) * 4;
    if (i >= (size_t)MQ*EMBED) return;
    float4 va = *(const float4*)(a + i);
    float4 vb = *(const float4*)(b + i);
    float4 vc = *(const float4*)(c + i);
    *(__half2*)(ha + i)     = __floats2half2_rn(va.x, va.y);
    *(__half2*)(ha + i + 2) = __floats2half2_rn(va.z, va.w);
    *(__half2*)(hb + i)     = __floats2half2_rn(vb.x, vb.y);
    *(__half2*)(hb + i + 2) = __floats2half2_rn(vb.z, vb.w);
    *(__half2*)(hc + i)     = __floats2half2_rn(vc.x, vc.y);
    *(__half2*)(hc + i + 2) = __floats2half2_rn(vc.z, vc.w);
}

// ---------------- weight transpose + fp16 convert ----------------
struct WPtrs { const float* s[8]; };

__global__ void twr_all(WPtrs P, __half* __restrict__ wh)
{
    const int z = blockIdx.z;
    const int K = (z == 7) ? FF : EMBED;
    const int N = (z == 6) ? FF : EMBED;
    const int n0 = blockIdx.x * 32, k0 = blockIdx.y * 32;
    if (n0 >= N || k0 >= K) return;
    const float* src = P.s[z];
    size_t off = (z <= 5) ? (size_t)z * WSZ : (z == 6 ? (size_t)6*WSZ : (size_t)6*WSZ + WFSZ);
    __half* dst = wh + off;

    __shared__ float t[32][33];
    #pragma unroll
    for (int i = 0; i < 32; i += 8)
        t[threadIdx.y + i][threadIdx.x] =
            src[(size_t)(k0 + threadIdx.y + i) * N + n0 + threadIdx.x];
    __syncthreads();
    #pragma unroll
    for (int i = 0; i < 32; i += 8)
        dst[(size_t)(n0 + threadIdx.y + i) * K + k0 + threadIdx.x] =
            __float2half(t[threadIdx.x][threadIdx.y + i]);
}

// ---------------- fp16 GEMM 128x128, K-stage 64, ldmatrix + 3-stage cp.async ----------------
// EPI bit0 = +residual R (fp32), bit1 = exact GELU, bit3 = fp16 output,
// bit4 = per-head L2 normalize (implies fp16 output; requires N=768 layout)
#define HG_STAGE 36864
#define HG_SMEM  (3 * HG_STAGE)   /* 110592 */

template<int EPI>
__global__ __launch_bounds__(256, 2)
void hgemm(const __half* __restrict__ A, const __half* __restrict__ Wt,
           const float* __restrict__ bias, const float* __restrict__ R,
           void* __restrict__ Cv, int M, int N, int K)
{
    extern __shared__ char smem[];

    const int tid  = threadIdx.x;
    const int lane = tid & 31;
    const int warp = tid >> 5;
    const int wm   = warp & 3;
    const int wn   = warp >> 2;
    const int bm   = blockIdx.y * 128;
    const int bn   = blockIdx.x * 128;
    const int NT   = K / 64;

    float acc[2][8][4];
    #pragma unroll
    for (int mi = 0; mi < 2; mi++)
        #pragma unroll
        for (int ni = 0; ni < 8; ni++)
            #pragma unroll
            for (int t = 0; t < 4; t++) acc[mi][ni][t] = 0.f;

    const int g  = lane >> 3;
    const int ri = lane & 7;
    const int rowA_off = (wm*32 + (g & 1)*8 + ri) * 144 + (g >> 1)*16;
    const int rowB_off = 18432 + (wn*64 + (g >> 1)*8 + ri) * 144 + (g & 1)*16;

    #define HG_PREFETCH(s)  do {                                                     \
        char* _b = smem + ((s) % 3) * HG_STAGE;                                      \
        const int _k0 = (s) * 64;                                                    \
        _Pragma("unroll")                                                            \
        for (int _i = 0; _i < 4; _i++) {                                             \
            int _id = tid + 256*_i;                                                  \
            int _r = _id >> 3, _c = _id & 7;                                         \
            cpasync16(_b + _r*144 + _c*16,         A  + (size_t)(bm + _r) * K + _k0 + _c*8); \
            cpasync16(_b + 18432 + _r*144 + _c*16, Wt + (size_t)(bn + _r) * K + _k0 + _c*8); \
        }                                                                            \
        CP_COMMIT();                                                                 \
    } while (0)

    HG_PREFETCH(0);
    HG_PREFETCH(1);

    for (int s = 0; s < NT; s++) {
        if (s + 1 < NT) { asm volatile("cp.async.wait_group 1;"); }
        else            { asm volatile("cp.async.wait_group 0;"); }
        __syncthreads();
        if (s + 2 < NT) HG_PREFETCH(s + 2);

        const uint32_t buf = smem_u32(smem + (s % 3) * HG_STAGE);
        #pragma unroll
        for (int kk = 0; kk < 4; kk++) {
            uint32_t a[2][4];
            #pragma unroll
            for (int mi = 0; mi < 2; mi++)
                ldsm_x4(a[mi], buf + rowA_off + mi*16*144 + kk*32);
            uint32_t b4[4][4];
            #pragma unroll
            for (int p = 0; p < 4; p++)
                ldsm_x4(b4[p], buf + rowB_off + p*16*144 + kk*32);
            #pragma unroll
            for (int mi = 0; mi < 2; mi++)
                #pragma unroll
                for (int ni = 0; ni < 8; ni++)
                    mma_f16(acc[mi][ni], a[mi], &b4[ni >> 1][(ni & 1)*2]);
        }
    }
    #undef HG_PREFETCH

    if (EPI & 16) {
        // fused per-head L2 normalize: one warp's 64-col tile == one head.
        // Each row's 64 head values live in the 4 lanes of a quad (lane>>2 fixed).
        #pragma unroll
        for (int mi = 0; mi < 2; mi++) {
            const int r0 = bm + wm*32 + mi*16 + (lane>>2);
            float vv[2][16];
            #pragma unroll
            for (int ni = 0; ni < 8; ni++) {
                const int c = bn + wn*64 + ni*8 + 2*(lane & 3);
                const float2 bb = *(const float2*)(bias + c);
                vv[0][2*ni]   = acc[mi][ni][0] + bb.x;
                vv[0][2*ni+1] = acc[mi][ni][1] + bb.y;
                vv[1][2*ni]   = acc[mi][ni][2] + bb.x;
                vv[1][2*ni+1] = acc[mi][ni][3] + bb.y;
            }
            #pragma unroll
            for (int hf = 0; hf < 2; hf++) {
                float ss = 0.f;
                #pragma unroll
                for (int j = 0; j < 16; j++) ss += vv[hf][j] * vv[hf][j];
                ss += __shfl_xor_sync(0xffffffffu, ss, 1);
                ss += __shfl_xor_sync(0xffffffffu, ss, 2);
                const float inv = 1.f / fmaxf(sqrtf(ss), 1e-12f);
                const int r = r0 + hf*8;
                #pragma unroll
                for (int ni = 0; ni < 8; ni++) {
                    const int c = bn + wn*64 + ni*8 + 2*(lane & 3);
                    *(__half2*)((__half*)Cv + (size_t)r * N + c) =
                        __floats2half2_rn(vv[hf][2*ni] * inv, vv[hf][2*ni+1] * inv);
                }
            }
        }
    } else {
        #pragma unroll
        for (int mi = 0; mi < 2; mi++) {
            const int r0 = bm + wm*32 + mi*16 + (lane>>2);
            #pragma unroll
            for (int ni = 0; ni < 8; ni++) {
                const int c = bn + wn*64 + ni*8 + 2*(lane & 3);
                const float2 bb = *(const float2*)(bias + c);
                #pragma unroll
                for (int half_ = 0; half_ < 2; half_++) {
                    const int r = r0 + half_*8;
                    float v0 = acc[mi][ni][2*half_+0] + bb.x;
                    float v1 = acc[mi][ni][2*half_+1] + bb.y;
                    if (EPI & 1) {
                        const float2 rr = *(const float2*)(R + (size_t)r * N + c);
                        v0 += rr.x; v1 += rr.y;
                    }
                    if (EPI & 2) {
                        v0 = 0.5f * v0 * (1.f + erff(v0 * 0.70710678118654752f));
                        v1 = 0.5f * v1 * (1.f + erff(v1 * 0.70710678118654752f));
                    }
                    if (EPI & 8)
                        *(__half2*)((__half*)Cv + (size_t)r * N + c) = __floats2half2_rn(v0, v1);
                    else
                        *(float2*)((float*)Cv + (size_t)r * N + c) = make_float2(v0, v1);
                }
            }
        }
    }
}

// ---------------- V transpose: hv fp16 [b*Lk+t][E] -> vt fp16 [b, E][Lk] ----------------
__global__ void vtrans_kernel(const __half* __restrict__ vp, __half* __restrict__ vt)
{
    const int t0 = blockIdx.x * 32;
    const int d0 = blockIdx.y * 32;
    const int b  = blockIdx.z;
    __shared__ float t[32][33];
    #pragma unroll
    for (int i = 0; i < 32; i += 8)
        t[threadIdx.y + i][threadIdx.x] =
            __half2float(vp[(size_t)(b*LK + t0 + threadIdx.y + i) * EMBED + d0 + threadIdx.x]);
    __syncthreads();
    #pragma unroll
    for (int i = 0; i < 32; i += 8)
        vt[(size_t)(b*EMBED + d0 + threadIdx.y + i) * LK + t0 + threadIdx.x] =
            __float2half(t[threadIdx.x][threadIdx.y + i]);
}

// ---------------- LayerNorm over 768 ----------------
template<bool DUAL>
__global__ void layernorm_kernel(const float* __restrict__ x,
                                 const float* __restrict__ g,
                                 const float* __restrict__ b,
                                 float* __restrict__ y, __half* __restrict__ yh)
{
    const int row = blockIdx.x;
    const float* xr = x + (size_t)row * EMBED;
    const int tid = threadIdx.x;

    float v0 = xr[tid], v1 = xr[tid + 256], v2 = xr[tid + 512];

    __shared__ float red[8];
    float s = v0 + v1 + v2;
    #pragma unroll
    for (int m = 16; m; m >>= 1) s += __shfl_xor_sync(0xffffffffu, s, m);
    if ((tid & 31) == 0) red[tid >> 5] = s;
    __syncthreads();
    s = 0.f;
    #pragma unroll
    for (int w = 0; w < 8; w++) s += red[w];
    const float mu = s * (1.f / EMBED);
    __syncthreads();

    float d0 = v0 - mu, d1 = v1 - mu, d2 = v2 - mu;
    float ss = d0*d0 + d1*d1 + d2*d2;
    #pragma unroll
    for (int m = 16; m; m >>= 1) ss += __shfl_xor_sync(0xffffffffu, ss, m);
    if ((tid & 31) == 0) red[tid >> 5] = ss;
    __syncthreads();
    ss = 0.f;
    #pragma unroll
    for (int w = 0; w < 8; w++) ss += red[w];
    const float inv = rsqrtf(ss * (1.f / EMBED) + 1e-5f);

    float o0 = d0 * inv * g[tid]       + b[tid];
    float o1 = d1 * inv * g[tid + 256] + b[tid + 256];
    float o2 = d2 * inv * g[tid + 512] + b[tid + 512];
    float* yr = y + (size_t)row * EMBED;
    yr[tid] = o0; yr[tid + 256] = o1; yr[tid + 512] = o2;
    if (DUAL) {
        __half* hr = yh + (size_t)row * EMBED;
        hr[tid] = __float2half(o0);
        hr[tid + 256] = __float2half(o1);
        hr[tid + 512] = __float2half(o2);
    }
}

// ---------------- fp16 flash attention, ldmatrix frags (proven from R7) ----------------
#define ATT_SMEM (7 * 64 * 72 * 2)

__global__ __launch_bounds__(128)
void attn_kernel(const __half* __restrict__ q, const __half* __restrict__ k,
                 const __half* __restrict__ vt, __half* __restrict__ out)
{
    extern __shared__ __half hsm[];
    __half* Qs    = hsm;
    __half* Ks[2] = { Qs + 64*72,      Qs + 2*64*72 };
    __half* Vs[2] = { Qs + 3*64*72,    Qs + 4*64*72 };
    __half* Ps    = Qs + 5*64*72;

    const int tid  = threadIdx.x;
    const int lane = tid & 31;
    const int warp = tid >> 5;
    const int q0 = blockIdx.x * 64;
    const int h  = blockIdx.y;
    const int b  = blockIdx.z;

    const __half* qb  = q  + ((size_t)(b*LQ + q0)) * EMBED + h * HDIM;
    const __half* kb  = k  + ((size_t)(b*LK))      * EMBED + h * HDIM;
    const __half* vtb = vt + ((size_t)(b*EMBED + h*HDIM)) * LK;

    const int rl = tid >> 3;
    const int cl = (tid & 7) * 8;

    #pragma unroll
    for (int i = 0; i < 4; i++) {
        int r = rl + 16*i;
        cpasync16(Qs + r*72 + cl, qb + (size_t)r * EMBED + cl);
    }
    #pragma unroll
    for (int i = 0; i < 4; i++) {
        int r = rl + 16*i;
        cpasync16(Ks[0] + r*72 + cl, kb  + (size_t)r * EMBED + cl);
        cpasync16(Vs[0] + r*72 + cl, vtb + (size_t)r * LK + cl);
    }
    CP_COMMIT();

    float o[8][4];
    #pragma unroll
    for (int ni = 0; ni < 8; ni++)
        #pragma unroll
        for (int t = 0; t < 4; t++) o[ni][t] = 0.f;
    float l0 = 0.f, l1 = 0.f;

    __half* Pw = Ps + warp*16*72;
    const int rql = lane >> 2;

    const int g2 = lane >> 3, ri = lane & 7;
    const uint32_t aQoff = (uint32_t)((warp*16 + (g2 & 1)*8 + ri) * 144 + (g2 >> 1)*16);
    const uint32_t aPoff = (uint32_t)(((g2 & 1)*8 + ri) * 144 + (g2 >> 1)*16);
    const uint32_t bOff  = (uint32_t)(((g2 >> 1)*8 + ri) * 144 + (g2 & 1)*16);
    const uint32_t qA  = smem_u32(Qs) + aQoff;
    const uint32_t pA  = smem_u32(Pw) + aPoff;

    for (int kt = 0; kt < LK/64; kt++) {
        asm volatile("cp.async.wait_group 0;");
        __syncthreads();

        const uint32_t kB = smem_u32(Ks[kt & 1]) + bOff;
        const uint32_t vB = smem_u32(Vs[kt & 1]) + bOff;

        if (kt + 1 < LK/64) {
            __half* ksn = Ks[(kt+1) & 1];
            __half* vsn = Vs[(kt+1) & 1];
            const __half* kp = kb  + (size_t)(kt+1) * 64 * EMBED;
            const __half* vp = vtb + (size_t)(kt+1) * 64;
            #pragma unroll
            for (int i = 0; i < 4; i++) {
                int r = rl + 16*i;
                cpasync16(ksn + r*72 + cl, kp + (size_t)r * EMBED + cl);
                cpasync16(vsn + r*72 + cl, vp + (size_t)r * LK + cl);
            }
            CP_COMMIT();
        }

        float s[8][4];
        #pragma unroll
        for (int ni = 0; ni < 8; ni++)
            #pragma unroll
            for (int t = 0; t < 4; t++) s[ni][t] = 0.f;

        #pragma unroll
        for (int kk = 0; kk < 4; kk++) {
            uint32_t a[4];
            ldsm_x4(a, qA + kk*32);
            uint32_t bf4[4][4];
            #pragma unroll
            for (int p = 0; p < 4; p++)
                ldsm_x4(bf4[p], kB + p*16*144 + kk*32);
            #pragma unroll
            for (int ni = 0; ni < 8; ni++)
                mma_f16(s[ni], a, &bf4[ni >> 1][(ni & 1)*2]);
        }

        #pragma unroll
        for (int ni = 0; ni < 8; ni++) {
            float p0 = __expf(s[ni][0] - 1.f);
            float p1 = __expf(s[ni][1] - 1.f);
            float p2 = __expf(s[ni][2] - 1.f);
            float p3 = __expf(s[ni][3] - 1.f);
            l0 += p0 + p1;
            l1 += p2 + p3;
            __half* pp = Pw + rql*72 + ni*8 + 2*(lane & 3);
            *(__half2*)pp          = __floats2half2_rn(p0, p1);
            *(__half2*)(pp + 8*72) = __floats2half2_rn(p2, p3);
        }
        __syncwarp();

        #pragma unroll
        for (int kk = 0; kk < 4; kk++) {
            uint32_t a[4];
            ldsm_x4(a, pA + kk*32);
            uint32_t bf4[4][4];
            #pragma unroll
            for (int p = 0; p < 4; p++)
                ldsm_x4(bf4[p], vB + p*16*144 + kk*32);
            #pragma unroll
            for (int ni = 0; ni < 8; ni++)
                mma_f16(o[ni], a, &bf4[ni >> 1][(ni & 1)*2]);
        }
    }

    l0 += __shfl_xor_sync(0xffffffffu, l0, 1);
    l0 += __shfl_xor_sync(0xffffffffu, l0, 2);
    l1 += __shfl_xor_sync(0xffffffffu, l1, 1);
    l1 += __shfl_xor_sync(0xffffffffu, l1, 2);
    const float inv0 = 1.f / l0, inv1 = 1.f / l1;

    const int r = b*LQ + q0 + warp*16 + rql;
    #pragma unroll
    for (int ni = 0; ni < 8; ni++) {
        const int c = h*HDIM + ni*8 + 2*(lane & 3);
        *(__half2*)(out + (size_t)r * EMBED + c)     = __floats2half2_rn(o[ni][0]*inv0, o[ni][1]*inv0);
        *(__half2*)(out + (size_t)(r+8) * EMBED + c) = __floats2half2_rn(o[ni][2]*inv1, o[ni][3]*inv1);
    }
}

// ---------------- launch ----------------
extern "C" void kernel_launch(void* const* d_in, const int* in_sizes, int n_in,
                              void* d_out, int out_size)
{
    const float* image_tokens = (const float*)d_in[0];
    const float* point_tokens = (const float*)d_in[1];
    const float* image_pos    = (const float*)d_in[2];
    const float* point_pos    = (const float*)d_in[3];
    const float* Wip = (const float*)d_in[4];   const float* bip = (const float*)d_in[5];
    const float* Wpp = (const float*)d_in[6];   const float* bpp = (const float*)d_in[7];
    const float* Wq  = (const float*)d_in[8];   const float* bq  = (const float*)d_in[9];
    const float* Wk  = (const float*)d_in[10];  const float* bk  = (const float*)d_in[11];
    const float* Wv  = (const float*)d_in[12];  const float* bv  = (const float*)d_in[13];
    const float* Wo  = (const float*)d_in[14];  const float* bo  = (const float*)d_in[15];
    const float* g1  = (const float*)d_in[16];  const float* b1  = (const float*)d_in[17];
    const float* g2  = (const float*)d_in[18];  const float* b2  = (const float*)d_in[19];
    const float* Wf1 = (const float*)d_in[20];  const float* bf1 = (const float*)d_in[21];
    const float* Wf2 = (const float*)d_in[22];  const float* bf2 = (const float*)d_in[23];
    float* out = (float*)d_out;

    float  *op, *ln1p, *f2p;
    __half *hA, *hB, *hv, *hip, *hpp, *hpt, *qh, *kh, *vt, *hat, *hln, *hff, *wh;
    cudaGetSymbolAddress((void**)&op,  g_o);
    cudaGetSymbolAddress((void**)&ln1p,g_ln1);
    cudaGetSymbolAddress((void**)&f2p, g_f2);
    cudaGetSymbolAddress((void**)&hA,  g_hA);
    cudaGetSymbolAddress((void**)&hB,  g_hB);
    cudaGetSymbolAddress((void**)&hv,  g_hv);
    cudaGetSymbolAddress((void**)&hip, g_hip);
    cudaGetSymbolAddress((void**)&hpp, g_hpp);
    cudaGetSymbolAddress((void**)&hpt, g_hpt);
    cudaGetSymbolAddress((void**)&qh,  g_qh);
    cudaGetSymbolAddress((void**)&kh,  g_kh);
    cudaGetSymbolAddress((void**)&vt,  g_vt);
    cudaGetSymbolAddress((void**)&hat, g_hat);
    cudaGetSymbolAddress((void**)&hln, g_hln);
    cudaGetSymbolAddress((void**)&hff, g_hff);
    cudaGetSymbolAddress((void**)&wh,  g_wh);

    __half* WipT = wh + 0*WSZ;
    __half* WppT = wh + 1*WSZ;
    __half* WqT  = wh + 2*WSZ;
    __half* WkT  = wh + 3*WSZ;
    __half* WvT  = wh + 4*WSZ;
    __half* WoT  = wh + 5*WSZ;
    __half* Wf1T = wh + 6*WSZ;
    __half* Wf2T = wh + 6*WSZ + WFSZ;

    static cudaStream_t s1 = nullptr, s2 = nullptr;
    static cudaEvent_t evA = nullptr, evK = nullptr, evV = nullptr;
    if (!s1) {
        cudaStreamCreateWithFlags(&s1, cudaStreamNonBlocking);
        cudaStreamCreateWithFlags(&s2, cudaStreamNonBlocking);
        cudaEventCreateWithFlags(&evA, cudaEventDisableTiming);
        cudaEventCreateWithFlags(&evK, cudaEventDisableTiming);
        cudaEventCreateWithFlags(&evV, cudaEventDisableTiming);
    }

    cudaFuncSetAttribute(hgemm<1>,  cudaFuncAttributeMaxDynamicSharedMemorySize, HG_SMEM);
    cudaFuncSetAttribute(hgemm<8>,  cudaFuncAttributeMaxDynamicSharedMemorySize, HG_SMEM);
    cudaFuncSetAttribute(hgemm<9>,  cudaFuncAttributeMaxDynamicSharedMemorySize, HG_SMEM);
    cudaFuncSetAttribute(hgemm<10>, cudaFuncAttributeMaxDynamicSharedMemorySize, HG_SMEM);
    cudaFuncSetAttribute(hgemm<16>, cudaFuncAttributeMaxDynamicSharedMemorySize, HG_SMEM);
    cudaFuncSetAttribute(attn_kernel, cudaFuncAttributeMaxDynamicSharedMemorySize, ATT_SMEM);

    // prep (origin stream), then fork via evA (capture-legal: first side-stream op is a wait)
    WPtrs P;
    P.s[0]=Wip; P.s[1]=Wpp; P.s[2]=Wq; P.s[3]=Wk; P.s[4]=Wv; P.s[5]=Wo; P.s[6]=Wf1; P.s[7]=Wf2;
    twr_all<<<dim3(48, 48, 8), dim3(32, 8)>>>(P, wh);
    cvt3<<<(MQ*EMBED/4 + 255)/256, 256>>>(image_pos, point_pos, point_tokens, hip, hpp, hpt);
    cudaEventRecord(evA, 0);

    // branch Q (s0): ip-proj(+res, fp16) -> q-proj (+fused l2norm, fp16)
    hgemm<9><<<dim3(EMBED/128, MQ/128), 256, HG_SMEM>>>(hip, WipT, bip, image_tokens, hA, MQ, EMBED, EMBED);
    hgemm<16><<<dim3(EMBED/128, MQ/128), 256, HG_SMEM>>>(hA, WqT, bq, nullptr, qh, MQ, EMBED, EMBED);

    // branch K (s1): pp-proj(+res, fp16) -> k-proj (+fused l2norm, fp16)
    cudaStreamWaitEvent(s1, evA, 0);
    hgemm<9><<<dim3(EMBED/128, MK/128), 256, HG_SMEM, s1>>>(hpp, WppT, bpp, point_tokens, hB, MK, EMBED, EMBED);
    hgemm<16><<<dim3(EMBED/128, MK/128), 256, HG_SMEM, s1>>>(hB, WkT, bk, nullptr, kh, MK, EMBED, EMBED);
    cudaEventRecord(evK, s1);

    // branch V (s2): v-proj (fp16) -> vtrans (fp16)
    cudaStreamWaitEvent(s2, evA, 0);
    hgemm<8><<<dim3(EMBED/128, MK/128), 256, HG_SMEM, s2>>>(hpt, WvT, bv, nullptr, hv, MK, EMBED, EMBED);
    vtrans_kernel<<<dim3(LK/32, EMBED/32, BATCH), dim3(32, 8), 0, s2>>>(hv, vt);
    cudaEventRecord(evV, s2);

    // join, attention, tail (s0)
    cudaStreamWaitEvent(0, evK, 0);
    cudaStreamWaitEvent(0, evV, 0);
    attn_kernel<<<dim3(LQ/64, HEADS, BATCH), 128, ATT_SMEM>>>(qh, kh, vt, hat);
    hgemm<1><<<dim3(EMBED/128, MQ/128), 256, HG_SMEM>>>(hat, WoT, bo, image_tokens, op, MQ, EMBED, EMBED);
    layernorm_kernel<true><<<MQ, 256>>>(op, g1, b1, ln1p, hln);
    hgemm<10><<<dim3(FF/128, MQ/128), 256, HG_SMEM>>>(hln, Wf1T, bf1, nullptr, hff, MQ, FF, EMBED);
    hgemm<1><<<dim3(EMBED/128, MQ/128), 256, HG_SMEM>>>(hff, Wf2T, bf2, ln1p, f2p, MQ, EMBED, FF);
    layernorm_kernel<false><<<MQ, 256>>>(f2p, g2, b2, out, nullptr);
}

// round 11
// speedup vs baseline: 1.3719x; 1.0580x over previous
#include <cuda_runtime.h>
#include <cuda_fp16.h>
#include <math.h>
#include <stdint.h>

#define EMBED 768
#define HEADS 12
#define HDIM  64
#define FF    1536
#define BATCH 4
#define LQ    2048
#define LK    2048
#define MQ    (BATCH*LQ)   /* 8192 */
#define MK    (BATCH*LK)   /* 8192 */
#define WSZ   (EMBED*EMBED)
#define WFSZ  (EMBED*FF)

// ---------------- scratch (no allocations allowed) ----------------
__device__ float  g_o  [MQ*EMBED];
__device__ float  g_ln1[MQ*EMBED];
__device__ float  g_f2 [MQ*EMBED];
__device__ __half g_hA [MQ*EMBED];      // q-chain intermediate fp16
__device__ __half g_hB [MK*EMBED];      // k-chain intermediate fp16
__device__ __half g_hv [MK*EMBED];      // v projection fp16
__device__ __half g_hip[MQ*EMBED];      // image_pos fp16
__device__ __half g_hpp[MK*EMBED];      // point_pos fp16
__device__ __half g_hpt[MK*EMBED];      // point_tokens fp16
__device__ __half g_qh [MQ*EMBED];
__device__ __half g_kh [MK*EMBED];
__device__ __half g_vt [BATCH*EMBED*LK];
__device__ __half g_hat[MQ*EMBED];
__device__ __half g_hln[MQ*EMBED];
__device__ __half g_hff[MQ*FF];
__device__ __half g_wh [6*WSZ + 2*WFSZ]; // transposed fp16 weights Wt[n][k]

// ---------------- helpers ----------------
__device__ __forceinline__ void cpasync16(void* s, const void* g) {
    uint32_t sa = (uint32_t)__cvta_generic_to_shared(s);
    asm volatile("cp.async.cg.shared.global [%0], [%1], 16;" :: "r"(sa), "l"(g));
}
#define CP_COMMIT() asm volatile("cp.async.commit_group;")

__device__ __forceinline__ uint32_t smem_u32(const void* p) {
    return (uint32_t)__cvta_generic_to_shared(p);
}

__device__ __forceinline__ void mma_f16(float c[4], const uint32_t a[4], const uint32_t b[2])
{
    asm volatile(
        "mma.sync.aligned.m16n8k16.row.col.f32.f16.f16.f32 "
        "{%0,%1,%2,%3}, {%4,%5,%6,%7}, {%8,%9}, {%0,%1,%2,%3};"
        : "+f"(c[0]), "+f"(c[1]), "+f"(c[2]), "+f"(c[3])
        : "r"(a[0]), "r"(a[1]), "r"(a[2]), "r"(a[3]), "r"(b[0]), "r"(b[1]));
}

__device__ __forceinline__ void ldsm_x4(uint32_t r[4], uint32_t addr) {
    asm volatile("ldmatrix.sync.aligned.m8n8.x4.shared.b16 {%0,%1,%2,%3}, [%4];"
        : "=r"(r[0]), "=r"(r[1]), "=r"(r[2]), "=r"(r[3]) : "r"(addr));
}

__device__ __forceinline__ uint32_t pack2(float x, float y) {
    __half2 h = __floats2half2_rn(x, y);
    return *(uint32_t*)&h;
}

// ---------------- prep: fp16 copies of the three A-side inputs ----------------
__global__ void cvt3(const float* __restrict__ a, const float* __restrict__ b,
                     const float* __restrict__ c, __half* __restrict__ ha,
                     __half* __restrict__ hb, __half* __restrict__ hc)
{
    size_t i = ((size_t)blockIdx.x * 256 + threadIdx.x) * 4;
    if (i >= (size_t)MQ*EMBED) return;
    float4 va = *(const float4*)(a + i);
    float4 vb = *(const float4*)(b + i);
    float4 vc = *(const float4*)(c + i);
    *(__half2*)(ha + i)     = __floats2half2_rn(va.x, va.y);
    *(__half2*)(ha + i + 2) = __floats2half2_rn(va.z, va.w);
    *(__half2*)(hb + i)     = __floats2half2_rn(vb.x, vb.y);
    *(__half2*)(hb + i + 2) = __floats2half2_rn(vb.z, vb.w);
    *(__half2*)(hc + i)     = __floats2half2_rn(vc.x, vc.y);
    *(__half2*)(hc + i + 2) = __floats2half2_rn(vc.z, vc.w);
}

// ---------------- weight transpose + fp16 convert ----------------
struct WPtrs { const float* s[8]; };

__global__ void twr_all(WPtrs P, __half* __restrict__ wh)
{
    const int z = blockIdx.z;
    const int K = (z == 7) ? FF : EMBED;
    const int N = (z == 6) ? FF : EMBED;
    const int n0 = blockIdx.x * 32, k0 = blockIdx.y * 32;
    if (n0 >= N || k0 >= K) return;
    const float* src = P.s[z];
    size_t off = (z <= 5) ? (size_t)z * WSZ : (z == 6 ? (size_t)6*WSZ : (size_t)6*WSZ + WFSZ);
    __half* dst = wh + off;

    __shared__ float t[32][33];
    #pragma unroll
    for (int i = 0; i < 32; i += 8)
        t[threadIdx.y + i][threadIdx.x] =
            src[(size_t)(k0 + threadIdx.y + i) * N + n0 + threadIdx.x];
    __syncthreads();
    #pragma unroll
    for (int i = 0; i < 32; i += 8)
        dst[(size_t)(n0 + threadIdx.y + i) * K + k0 + threadIdx.x] =
            __float2half(t[threadIdx.x][threadIdx.y + i]);
}

// ---------------- fp16 GEMM 128x128, K-stage 64, ldmatrix + 3-stage cp.async ----------------
// EPI bit0 = +residual R (fp32), bit1 = exact GELU, bit3 = fp16 output,
// bit4 = per-head L2 normalize (implies fp16 output; requires N=768 layout)
#define HG_STAGE 36864
#define HG_SMEM  (3 * HG_STAGE)   /* 110592 */

template<int EPI>
__global__ __launch_bounds__(256, 2)
void hgemm(const __half* __restrict__ A, const __half* __restrict__ Wt,
           const float* __restrict__ bias, const float* __restrict__ R,
           void* __restrict__ Cv, int M, int N, int K)
{
    extern __shared__ char smem[];

    const int tid  = threadIdx.x;
    const int lane = tid & 31;
    const int warp = tid >> 5;
    const int wm   = warp & 3;
    const int wn   = warp >> 2;
    const int bm   = blockIdx.y * 128;
    const int bn   = blockIdx.x * 128;
    const int NT   = K / 64;

    float acc[2][8][4];
    #pragma unroll
    for (int mi = 0; mi < 2; mi++)
        #pragma unroll
        for (int ni = 0; ni < 8; ni++)
            #pragma unroll
            for (int t = 0; t < 4; t++) acc[mi][ni][t] = 0.f;

    const int g  = lane >> 3;
    const int ri = lane & 7;
    const int rowA_off = (wm*32 + (g & 1)*8 + ri) * 144 + (g >> 1)*16;
    const int rowB_off = 18432 + (wn*64 + (g >> 1)*8 + ri) * 144 + (g & 1)*16;

    #define HG_PREFETCH(s)  do {                                                     \
        char* _b = smem + ((s) % 3) * HG_STAGE;                                      \
        const int _k0 = (s) * 64;                                                    \
        _Pragma("unroll")                                                            \
        for (int _i = 0; _i < 4; _i++) {                                             \
            int _id = tid + 256*_i;                                                  \
            int _r = _id >> 3, _c = _id & 7;                                         \
            cpasync16(_b + _r*144 + _c*16,         A  + (size_t)(bm + _r) * K + _k0 + _c*8); \
            cpasync16(_b + 18432 + _r*144 + _c*16, Wt + (size_t)(bn + _r) * K + _k0 + _c*8); \
        }                                                                            \
        CP_COMMIT();                                                                 \
    } while (0)

    HG_PREFETCH(0);
    HG_PREFETCH(1);

    for (int s = 0; s < NT; s++) {
        if (s + 1 < NT) { asm volatile("cp.async.wait_group 1;"); }
        else            { asm volatile("cp.async.wait_group 0;"); }
        __syncthreads();
        if (s + 2 < NT) HG_PREFETCH(s + 2);

        const uint32_t buf = smem_u32(smem + (s % 3) * HG_STAGE);
        #pragma unroll
        for (int kk = 0; kk < 4; kk++) {
            uint32_t a[2][4];
            #pragma unroll
            for (int mi = 0; mi < 2; mi++)
                ldsm_x4(a[mi], buf + rowA_off + mi*16*144 + kk*32);
            uint32_t b4[4][4];
            #pragma unroll
            for (int p = 0; p < 4; p++)
                ldsm_x4(b4[p], buf + rowB_off + p*16*144 + kk*32);
            #pragma unroll
            for (int mi = 0; mi < 2; mi++)
                #pragma unroll
                for (int ni = 0; ni < 8; ni++)
                    mma_f16(acc[mi][ni], a[mi], &b4[ni >> 1][(ni & 1)*2]);
        }
    }
    #undef HG_PREFETCH

    if (EPI & 16) {
        // fused per-head L2 normalize: one warp's 64-col tile == one head.
        #pragma unroll
        for (int mi = 0; mi < 2; mi++) {
            const int r0 = bm + wm*32 + mi*16 + (lane>>2);
            float vv[2][16];
            #pragma unroll
            for (int ni = 0; ni < 8; ni++) {
                const int c = bn + wn*64 + ni*8 + 2*(lane & 3);
                const float2 bb = *(const float2*)(bias + c);
                vv[0][2*ni]   = acc[mi][ni][0] + bb.x;
                vv[0][2*ni+1] = acc[mi][ni][1] + bb.y;
                vv[1][2*ni]   = acc[mi][ni][2] + bb.x;
                vv[1][2*ni+1] = acc[mi][ni][3] + bb.y;
            }
            #pragma unroll
            for (int hf = 0; hf < 2; hf++) {
                float ss = 0.f;
                #pragma unroll
                for (int j = 0; j < 16; j++) ss += vv[hf][j] * vv[hf][j];
                ss += __shfl_xor_sync(0xffffffffu, ss, 1);
                ss += __shfl_xor_sync(0xffffffffu, ss, 2);
                const float inv = 1.f / fmaxf(sqrtf(ss), 1e-12f);
                const int r = r0 + hf*8;
                #pragma unroll
                for (int ni = 0; ni < 8; ni++) {
                    const int c = bn + wn*64 + ni*8 + 2*(lane & 3);
                    *(__half2*)((__half*)Cv + (size_t)r * N + c) =
                        __floats2half2_rn(vv[hf][2*ni] * inv, vv[hf][2*ni+1] * inv);
                }
            }
        }
    } else {
        #pragma unroll
        for (int mi = 0; mi < 2; mi++) {
            const int r0 = bm + wm*32 + mi*16 + (lane>>2);
            #pragma unroll
            for (int ni = 0; ni < 8; ni++) {
                const int c = bn + wn*64 + ni*8 + 2*(lane & 3);
                const float2 bb = *(const float2*)(bias + c);
                #pragma unroll
                for (int half_ = 0; half_ < 2; half_++) {
                    const int r = r0 + half_*8;
                    float v0 = acc[mi][ni][2*half_+0] + bb.x;
                    float v1 = acc[mi][ni][2*half_+1] + bb.y;
                    if (EPI & 1) {
                        const float2 rr = *(const float2*)(R + (size_t)r * N + c);
                        v0 += rr.x; v1 += rr.y;
                    }
                    if (EPI & 2) {
                        v0 = 0.5f * v0 * (1.f + erff(v0 * 0.70710678118654752f));
                        v1 = 0.5f * v1 * (1.f + erff(v1 * 0.70710678118654752f));
                    }
                    if (EPI & 8)
                        *(__half2*)((__half*)Cv + (size_t)r * N + c) = __floats2half2_rn(v0, v1);
                    else
                        *(float2*)((float*)Cv + (size_t)r * N + c) = make_float2(v0, v1);
                }
            }
        }
    }
}

// ---------------- V transpose: hv fp16 [b*Lk+t][E] -> vt fp16 [b, E][Lk] ----------------
__global__ void vtrans_kernel(const __half* __restrict__ vp, __half* __restrict__ vt)
{
    const int t0 = blockIdx.x * 32;
    const int d0 = blockIdx.y * 32;
    const int b  = blockIdx.z;
    __shared__ float t[32][33];
    #pragma unroll
    for (int i = 0; i < 32; i += 8)
        t[threadIdx.y + i][threadIdx.x] =
            __half2float(vp[(size_t)(b*LK + t0 + threadIdx.y + i) * EMBED + d0 + threadIdx.x]);
    __syncthreads();
    #pragma unroll
    for (int i = 0; i < 32; i += 8)
        vt[(size_t)(b*EMBED + d0 + threadIdx.y + i) * LK + t0 + threadIdx.x] =
            __float2half(t[threadIdx.x][threadIdx.y + i]);
}

// ---------------- LayerNorm over 768 ----------------
template<bool DUAL>
__global__ void layernorm_kernel(const float* __restrict__ x,
                                 const float* __restrict__ g,
                                 const float* __restrict__ b,
                                 float* __restrict__ y, __half* __restrict__ yh)
{
    const int row = blockIdx.x;
    const float* xr = x + (size_t)row * EMBED;
    const int tid = threadIdx.x;

    float v0 = xr[tid], v1 = xr[tid + 256], v2 = xr[tid + 512];

    __shared__ float red[8];
    float s = v0 + v1 + v2;
    #pragma unroll
    for (int m = 16; m; m >>= 1) s += __shfl_xor_sync(0xffffffffu, s, m);
    if ((tid & 31) == 0) red[tid >> 5] = s;
    __syncthreads();
    s = 0.f;
    #pragma unroll
    for (int w = 0; w < 8; w++) s += red[w];
    const float mu = s * (1.f / EMBED);
    __syncthreads();

    float d0 = v0 - mu, d1 = v1 - mu, d2 = v2 - mu;
    float ss = d0*d0 + d1*d1 + d2*d2;
    #pragma unroll
    for (int m = 16; m; m >>= 1) ss += __shfl_xor_sync(0xffffffffu, ss, m);
    if ((tid & 31) == 0) red[tid >> 5] = ss;
    __syncthreads();
    ss = 0.f;
    #pragma unroll
    for (int w = 0; w < 8; w++) ss += red[w];
    const float inv = rsqrtf(ss * (1.f / EMBED) + 1e-5f);

    float o0 = d0 * inv * g[tid]       + b[tid];
    float o1 = d1 * inv * g[tid + 256] + b[tid + 256];
    float o2 = d2 * inv * g[tid + 512] + b[tid + 512];
    float* yr = y + (size_t)row * EMBED;
    yr[tid] = o0; yr[tid + 256] = o1; yr[tid + 512] = o2;
    if (DUAL) {
        __half* hr = yh + (size_t)row * EMBED;
        hr[tid] = __float2half(o0);
        hr[tid + 256] = __float2half(o1);
        hr[tid + 512] = __float2half(o2);
    }
}

// ---------------- fp16 flash attention: 128-row q-tile, register-resident P ----------------
// scale-free: q,k unit vectors -> s in [-1,1] -> p = exp(s-1), no online max, no rescale.
// 256 thr / 8 warps (16 q-rows per warp); kv-tile 64, double-buffered.
// P stays in registers: S C-frag -> exp -> pack -> A-frag of P@V (FA2 identity). No P smem.
#define ATT_SMEM ((128*72 + 4*64*72) * 2)   /* 55296 B */

__global__ __launch_bounds__(256, 2)
void attn_kernel(const __half* __restrict__ q, const __half* __restrict__ k,
                 const __half* __restrict__ vt, __half* __restrict__ out)
{
    extern __shared__ __half hsm[];
    __half* Qs    = hsm;                            // [128][72]
    __half* Ks[2] = { hsm + 128*72,            hsm + 128*72 + 64*72 };
    __half* Vs[2] = { hsm + 128*72 + 2*64*72,  hsm + 128*72 + 3*64*72 };

    const int tid  = threadIdx.x;
    const int lane = tid & 31;
    const int warp = tid >> 5;          // 0..7
    const int q0 = blockIdx.x * 128;
    const int h  = blockIdx.y;
    const int b  = blockIdx.z;

    const __half* qb  = q  + ((size_t)(b*LQ + q0)) * EMBED + h * HDIM;
    const __half* kb  = k  + ((size_t)(b*LK))      * EMBED + h * HDIM;
    const __half* vtb = vt + ((size_t)(b*EMBED + h*HDIM)) * LK;

    const int rl = tid >> 3;            // 0..31
    const int cl = (tid & 7) * 8;       // halves 0..56

    // Q tile (128 rows) + stage-0 K/V (64 rows each), one commit group
    #pragma unroll
    for (int i = 0; i < 4; i++) {
        int r = rl + 32*i;
        cpasync16(Qs + r*72 + cl, qb + (size_t)r * EMBED + cl);
    }
    #pragma unroll
    for (int i = 0; i < 2; i++) {
        int r = rl + 32*i;
        cpasync16(Ks[0] + r*72 + cl, kb  + (size_t)r * EMBED + cl);
        cpasync16(Vs[0] + r*72 + cl, vtb + (size_t)r * LK + cl);
    }
    CP_COMMIT();

    float o[8][4];
    #pragma unroll
    for (int ni = 0; ni < 8; ni++)
        #pragma unroll
        for (int t = 0; t < 4; t++) o[ni][t] = 0.f;
    float l0 = 0.f, l1 = 0.f;

    const int rql = lane >> 2;
    const int g2 = lane >> 3, ri = lane & 7;
    const uint32_t aQoff = (uint32_t)((warp*16 + (g2 & 1)*8 + ri) * 144 + (g2 >> 1)*16);
    const uint32_t bOff  = (uint32_t)(((g2 >> 1)*8 + ri) * 144 + (g2 & 1)*16);
    const uint32_t qA    = smem_u32(Qs) + aQoff;

    uint32_t qf[4][4];                  // hoisted Q fragments (whole 16x64 warp tile)

    for (int kt = 0; kt < LK/64; kt++) {
        asm volatile("cp.async.wait_group 0;");
        __syncthreads();

        if (kt == 0) {
            #pragma unroll
            for (int kk = 0; kk < 4; kk++)
                ldsm_x4(qf[kk], qA + kk*32);
        }

        const uint32_t kB = smem_u32(Ks[kt & 1]) + bOff;
        const uint32_t vB = smem_u32(Vs[kt & 1]) + bOff;

        if (kt + 1 < LK/64) {
            __half* ksn = Ks[(kt+1) & 1];
            __half* vsn = Vs[(kt+1) & 1];
            const __half* kp = kb  + (size_t)(kt+1) * 64 * EMBED;
            const __half* vp = vtb + (size_t)(kt+1) * 64;
            #pragma unroll
            for (int i = 0; i < 2; i++) {
                int r = rl + 32*i;
                cpasync16(ksn + r*72 + cl, kp + (size_t)r * EMBED + cl);
                cpasync16(vsn + r*72 + cl, vp + (size_t)r * LK + cl);
            }
            CP_COMMIT();
        }

        // S = Q @ K^T  (16 q-rows x 64 keys per warp)
        float s[8][4];
        #pragma unroll
        for (int ni = 0; ni < 8; ni++)
            #pragma unroll
            for (int t = 0; t < 4; t++) s[ni][t] = 0.f;

        #pragma unroll
        for (int kk = 0; kk < 4; kk++) {
            uint32_t bf4[4][4];
            #pragma unroll
            for (int p = 0; p < 4; p++)
                ldsm_x4(bf4[p], kB + p*16*144 + kk*32);
            #pragma unroll
            for (int ni = 0; ni < 8; ni++)
                mma_f16(s[ni], qf[kk], &bf4[ni >> 1][(ni & 1)*2]);
        }

        // p = exp(s - 1) -> pack directly into P@V A-frags (registers only)
        uint32_t ph[8][2];
        #pragma unroll
        for (int ni = 0; ni < 8; ni++) {
            float p0 = __expf(s[ni][0] - 1.f);
            float p1 = __expf(s[ni][1] - 1.f);
            float p2 = __expf(s[ni][2] - 1.f);
            float p3 = __expf(s[ni][3] - 1.f);
            l0 += p0 + p1;
            l1 += p2 + p3;
            ph[ni][0] = pack2(p0, p1);
            ph[ni][1] = pack2(p2, p3);
        }

        // O += P @ V  (A-frag from ph; B from Vs [d][key], k = keys)
        #pragma unroll
        for (int kk = 0; kk < 4; kk++) {
            uint32_t a[4] = { ph[2*kk][0], ph[2*kk][1], ph[2*kk+1][0], ph[2*kk+1][1] };
            uint32_t bf4[4][4];
            #pragma unroll
            for (int p = 0; p < 4; p++)
                ldsm_x4(bf4[p], vB + p*16*144 + kk*32);
            #pragma unroll
            for (int ni = 0; ni < 8; ni++)
                mma_f16(o[ni], a, &bf4[ni >> 1][(ni & 1)*2]);
        }
    }

    l0 += __shfl_xor_sync(0xffffffffu, l0, 1);
    l0 += __shfl_xor_sync(0xffffffffu, l0, 2);
    l1 += __shfl_xor_sync(0xffffffffu, l1, 1);
    l1 += __shfl_xor_sync(0xffffffffu, l1, 2);
    const float inv0 = 1.f / l0, inv1 = 1.f / l1;

    const int r = b*LQ + q0 + warp*16 + rql;
    #pragma unroll
    for (int ni = 0; ni < 8; ni++) {
        const int c = h*HDIM + ni*8 + 2*(lane & 3);
        *(__half2*)(out + (size_t)r * EMBED + c)     = __floats2half2_rn(o[ni][0]*inv0, o[ni][1]*inv0);
        *(__half2*)(out + (size_t)(r+8) * EMBED + c) = __floats2half2_rn(o[ni][2]*inv1, o[ni][3]*inv1);
    }
}

// ---------------- launch ----------------
extern "C" void kernel_launch(void* const* d_in, const int* in_sizes, int n_in,
                              void* d_out, int out_size)
{
    const float* image_tokens = (const float*)d_in[0];
    const float* point_tokens = (const float*)d_in[1];
    const float* image_pos    = (const float*)d_in[2];
    const float* point_pos    = (const float*)d_in[3];
    const float* Wip = (const float*)d_in[4];   const float* bip = (const float*)d_in[5];
    const float* Wpp = (const float*)d_in[6];   const float* bpp = (const float*)d_in[7];
    const float* Wq  = (const float*)d_in[8];   const float* bq  = (const float*)d_in[9];
    const float* Wk  = (const float*)d_in[10];  const float* bk  = (const float*)d_in[11];
    const float* Wv  = (const float*)d_in[12];  const float* bv  = (const float*)d_in[13];
    const float* Wo  = (const float*)d_in[14];  const float* bo  = (const float*)d_in[15];
    const float* g1  = (const float*)d_in[16];  const float* b1  = (const float*)d_in[17];
    const float* g2  = (const float*)d_in[18];  const float* b2  = (const float*)d_in[19];
    const float* Wf1 = (const float*)d_in[20];  const float* bf1 = (const float*)d_in[21];
    const float* Wf2 = (const float*)d_in[22];  const float* bf2 = (const float*)d_in[23];
    float* out = (float*)d_out;

    float  *op, *ln1p, *f2p;
    __half *hA, *hB, *hv, *hip, *hpp, *hpt, *qh, *kh, *vt, *hat, *hln, *hff, *wh;
    cudaGetSymbolAddress((void**)&op,  g_o);
    cudaGetSymbolAddress((void**)&ln1p,g_ln1);
    cudaGetSymbolAddress((void**)&f2p, g_f2);
    cudaGetSymbolAddress((void**)&hA,  g_hA);
    cudaGetSymbolAddress((void**)&hB,  g_hB);
    cudaGetSymbolAddress((void**)&hv,  g_hv);
    cudaGetSymbolAddress((void**)&hip, g_hip);
    cudaGetSymbolAddress((void**)&hpp, g_hpp);
    cudaGetSymbolAddress((void**)&hpt, g_hpt);
    cudaGetSymbolAddress((void**)&qh,  g_qh);
    cudaGetSymbolAddress((void**)&kh,  g_kh);
    cudaGetSymbolAddress((void**)&vt,  g_vt);
    cudaGetSymbolAddress((void**)&hat, g_hat);
    cudaGetSymbolAddress((void**)&hln, g_hln);
    cudaGetSymbolAddress((void**)&hff, g_hff);
    cudaGetSymbolAddress((void**)&wh,  g_wh);

    __half* WipT = wh + 0*WSZ;
    __half* WppT = wh + 1*WSZ;
    __half* WqT  = wh + 2*WSZ;
    __half* WkT  = wh + 3*WSZ;
    __half* WvT  = wh + 4*WSZ;
    __half* WoT  = wh + 5*WSZ;
    __half* Wf1T = wh + 6*WSZ;
    __half* Wf2T = wh + 6*WSZ + WFSZ;

    static cudaStream_t s1 = nullptr, s2 = nullptr;
    static cudaEvent_t evA = nullptr, evK = nullptr, evV = nullptr;
    if (!s1) {
        cudaStreamCreateWithFlags(&s1, cudaStreamNonBlocking);
        cudaStreamCreateWithFlags(&s2, cudaStreamNonBlocking);
        cudaEventCreateWithFlags(&evA, cudaEventDisableTiming);
        cudaEventCreateWithFlags(&evK, cudaEventDisableTiming);
        cudaEventCreateWithFlags(&evV, cudaEventDisableTiming);
    }

    cudaFuncSetAttribute(hgemm<1>,  cudaFuncAttributeMaxDynamicSharedMemorySize, HG_SMEM);
    cudaFuncSetAttribute(hgemm<8>,  cudaFuncAttributeMaxDynamicSharedMemorySize, HG_SMEM);
    cudaFuncSetAttribute(hgemm<9>,  cudaFuncAttributeMaxDynamicSharedMemorySize, HG_SMEM);
    cudaFuncSetAttribute(hgemm<10>, cudaFuncAttributeMaxDynamicSharedMemorySize, HG_SMEM);
    cudaFuncSetAttribute(hgemm<16>, cudaFuncAttributeMaxDynamicSharedMemorySize, HG_SMEM);
    cudaFuncSetAttribute(attn_kernel, cudaFuncAttributeMaxDynamicSharedMemorySize, ATT_SMEM);

    // prep (origin stream), then fork via evA (capture-legal: first side-stream op is a wait)
    WPtrs P;
    P.s[0]=Wip; P.s[1]=Wpp; P.s[2]=Wq; P.s[3]=Wk; P.s[4]=Wv; P.s[5]=Wo; P.s[6]=Wf1; P.s[7]=Wf2;
    twr_all<<<dim3(48, 48, 8), dim3(32, 8)>>>(P, wh);
    cvt3<<<(MQ*EMBED/4 + 255)/256, 256>>>(image_pos, point_pos, point_tokens, hip, hpp, hpt);
    cudaEventRecord(evA, 0);

    // branch Q (s0): ip-proj(+res, fp16) -> q-proj (+fused l2norm, fp16)
    hgemm<9><<<dim3(EMBED/128, MQ/128), 256, HG_SMEM>>>(hip, WipT, bip, image_tokens, hA, MQ, EMBED, EMBED);
    hgemm<16><<<dim3(EMBED/128, MQ/128), 256, HG_SMEM>>>(hA, WqT, bq, nullptr, qh, MQ, EMBED, EMBED);

    // branch K (s1): pp-proj(+res, fp16) -> k-proj (+fused l2norm, fp16)
    cudaStreamWaitEvent(s1, evA, 0);
    hgemm<9><<<dim3(EMBED/128, MK/128), 256, HG_SMEM, s1>>>(hpp, WppT, bpp, point_tokens, hB, MK, EMBED, EMBED);
    hgemm<16><<<dim3(EMBED/128, MK/128), 256, HG_SMEM, s1>>>(hB, WkT, bk, nullptr, kh, MK, EMBED, EMBED);
    cudaEventRecord(evK, s1);

    // branch V (s2): v-proj (fp16) -> vtrans (fp16)
    cudaStreamWaitEvent(s2, evA, 0);
    hgemm<8><<<dim3(EMBED/128, MK/128), 256, HG_SMEM, s2>>>(hpt, WvT, bv, nullptr, hv, MK, EMBED, EMBED);
    vtrans_kernel<<<dim3(LK/32, EMBED/32, BATCH), dim3(32, 8), 0, s2>>>(hv, vt);
    cudaEventRecord(evV, s2);

    // join, attention, tail (s0)
    cudaStreamWaitEvent(0, evK, 0);
    cudaStreamWaitEvent(0, evV, 0);
    attn_kernel<<<dim3(LQ/128, HEADS, BATCH), 256, ATT_SMEM>>>(qh, kh, vt, hat);
    hgemm<1><<<dim3(EMBED/128, MQ/128), 256, HG_SMEM>>>(hat, WoT, bo, image_tokens, op, MQ, EMBED, EMBED);
    layernorm_kernel<true><<<MQ, 256>>>(op, g1, b1, ln1p, hln);
    hgemm<10><<<dim3(FF/128, MQ/128), 256, HG_SMEM>>>(hln, Wf1T, bf1, nullptr, hff, MQ, FF, EMBED);
    hgemm<1><<<dim3(EMBED/128, MQ/128), 256, HG_SMEM>>>(hff, Wf2T, bf2, ln1p, f2p, MQ, EMBED, FF);
    layernorm_kernel<false><<<MQ, 256>>>(f2p, g2, b2, out, nullptr);
}

// round 12
// speedup vs baseline: 1.4625x; 1.0661x over previous
#include <cuda_runtime.h>
#include <cuda_fp16.h>
#include <math.h>
#include <stdint.h>

#define EMBED 768
#define HEADS 12
#define HDIM  64
#define FF    1536
#define BATCH 4
#define LQ    2048
#define LK    2048
#define MQ    (BATCH*LQ)   /* 8192 */
#define MK    (BATCH*LK)   /* 8192 */
#define MH    (MQ/2)       /* 4096 rows per chunk */
#define WSZ   (EMBED*EMBED)
#define WFSZ  (EMBED*FF)

// ---------------- scratch (no allocations allowed) ----------------
__device__ float  g_o  [MQ*EMBED];
__device__ float  g_ln1[MQ*EMBED];
__device__ float  g_f2 [MQ*EMBED];
__device__ __half g_hA [MQ*EMBED];
__device__ __half g_hB [MK*EMBED];
__device__ __half g_hv [MK*EMBED];
__device__ __half g_hip[MQ*EMBED];
__device__ __half g_hpp[MK*EMBED];
__device__ __half g_hpt[MK*EMBED];
__device__ __half g_qh [MQ*EMBED];
__device__ __half g_kh [MK*EMBED];
__device__ __half g_vt [BATCH*EMBED*LK];
__device__ __half g_hat[MQ*EMBED];
__device__ __half g_hln[MQ*EMBED];
__device__ __half g_hff[MQ*FF];
__device__ __half g_wh [6*WSZ + 2*WFSZ];

// ---------------- helpers ----------------
__device__ __forceinline__ void cpasync16(void* s, const void* g) {
    uint32_t sa = (uint32_t)__cvta_generic_to_shared(s);
    asm volatile("cp.async.cg.shared.global [%0], [%1], 16;" :: "r"(sa), "l"(g));
}
#define CP_COMMIT() asm volatile("cp.async.commit_group;")

__device__ __forceinline__ uint32_t smem_u32(const void* p) {
    return (uint32_t)__cvta_generic_to_shared(p);
}

__device__ __forceinline__ void mma_f16(float c[4], const uint32_t a[4], const uint32_t b[2])
{
    asm volatile(
        "mma.sync.aligned.m16n8k16.row.col.f32.f16.f16.f32 "
        "{%0,%1,%2,%3}, {%4,%5,%6,%7}, {%8,%9}, {%0,%1,%2,%3};"
        : "+f"(c[0]), "+f"(c[1]), "+f"(c[2]), "+f"(c[3])
        : "r"(a[0]), "r"(a[1]), "r"(a[2]), "r"(a[3]), "r"(b[0]), "r"(b[1]));
}

__device__ __forceinline__ void ldsm_x4(uint32_t r[4], uint32_t addr) {
    asm volatile("ldmatrix.sync.aligned.m8n8.x4.shared.b16 {%0,%1,%2,%3}, [%4];"
        : "=r"(r[0]), "=r"(r[1]), "=r"(r[2]), "=r"(r[3]) : "r"(addr));
}

__device__ __forceinline__ uint32_t pack2(float x, float y) {
    __half2 h = __floats2half2_rn(x, y);
    return *(uint32_t*)&h;
}

// ---------------- prep: fp16 copies of the three A-side inputs ----------------
__global__ void cvt3(const float* __restrict__ a, const float* __restrict__ b,
                     const float* __restrict__ c, __half* __restrict__ ha,
                     __half* __restrict__ hb, __half* __restrict__ hc)
{
    size_t i = ((size_t)blockIdx.x * 256 + threadIdx.x) * 4;
    if (i >= (size_t)MQ*EMBED) return;
    float4 va = *(const float4*)(a + i);
    float4 vb = *(const float4*)(b + i);
    float4 vc = *(const float4*)(c + i);
    *(__half2*)(ha + i)     = __floats2half2_rn(va.x, va.y);
    *(__half2*)(ha + i + 2) = __floats2half2_rn(va.z, va.w);
    *(__half2*)(hb + i)     = __floats2half2_rn(vb.x, vb.y);
    *(__half2*)(hb + i + 2) = __floats2half2_rn(vb.z, vb.w);
    *(__half2*)(hc + i)     = __floats2half2_rn(vc.x, vc.y);
    *(__half2*)(hc + i + 2) = __floats2half2_rn(vc.z, vc.w);
}

// ---------------- weight transpose + fp16 convert ----------------
struct WPtrs { const float* s[8]; };

__global__ void twr_all(WPtrs P, __half* __restrict__ wh)
{
    const int z = blockIdx.z;
    const int K = (z == 7) ? FF : EMBED;
    const int N = (z == 6) ? FF : EMBED;
    const int n0 = blockIdx.x * 32, k0 = blockIdx.y * 32;
    if (n0 >= N || k0 >= K) return;
    const float* src = P.s[z];
    size_t off = (z <= 5) ? (size_t)z * WSZ : (z == 6 ? (size_t)6*WSZ : (size_t)6*WSZ + WFSZ);
    __half* dst = wh + off;

    __shared__ float t[32][33];
    #pragma unroll
    for (int i = 0; i < 32; i += 8)
        t[threadIdx.y + i][threadIdx.x] =
            src[(size_t)(k0 + threadIdx.y + i) * N + n0 + threadIdx.x];
    __syncthreads();
    #pragma unroll
    for (int i = 0; i < 32; i += 8)
        dst[(size_t)(n0 + threadIdx.y + i) * K + k0 + threadIdx.x] =
            __float2half(t[threadIdx.x][threadIdx.y + i]);
}

// ---------------- fp16 GEMM 128x128, K-stage 64, ldmatrix + 3-stage cp.async ----------------
// EPI bit0 = +residual R (fp32), bit1 = exact GELU, bit3 = fp16 output,
// bit4 = per-head L2 normalize (implies fp16 output; requires N=768 layout)
#define HG_STAGE 36864
#define HG_SMEM  (3 * HG_STAGE)   /* 110592 */

template<int EPI>
__global__ __launch_bounds__(256, 2)
void hgemm(const __half* __restrict__ A, const __half* __restrict__ Wt,
           const float* __restrict__ bias, const float* __restrict__ R,
           void* __restrict__ Cv, int M, int N, int K)
{
    extern __shared__ char smem[];

    const int tid  = threadIdx.x;
    const int lane = tid & 31;
    const int warp = tid >> 5;
    const int wm   = warp & 3;
    const int wn   = warp >> 2;
    const int bm   = blockIdx.y * 128;
    const int bn   = blockIdx.x * 128;
    const int NT   = K / 64;

    float acc[2][8][4];
    #pragma unroll
    for (int mi = 0; mi < 2; mi++)
        #pragma unroll
        for (int ni = 0; ni < 8; ni++)
            #pragma unroll
            for (int t = 0; t < 4; t++) acc[mi][ni][t] = 0.f;

    const int g  = lane >> 3;
    const int ri = lane & 7;
    const int rowA_off = (wm*32 + (g & 1)*8 + ri) * 144 + (g >> 1)*16;
    const int rowB_off = 18432 + (wn*64 + (g >> 1)*8 + ri) * 144 + (g & 1)*16;

    #define HG_PREFETCH(s)  do {                                                     \
        char* _b = smem + ((s) % 3) * HG_STAGE;                                      \
        const int _k0 = (s) * 64;                                                    \
        _Pragma("unroll")                                                            \
        for (int _i = 0; _i < 4; _i++) {                                             \
            int _id = tid + 256*_i;                                                  \
            int _r = _id >> 3, _c = _id & 7;                                         \
            cpasync16(_b + _r*144 + _c*16,         A  + (size_t)(bm + _r) * K + _k0 + _c*8); \
            cpasync16(_b + 18432 + _r*144 + _c*16, Wt + (size_t)(bn + _r) * K + _k0 + _c*8); \
        }                                                                            \
        CP_COMMIT();                                                                 \
    } while (0)

    HG_PREFETCH(0);
    HG_PREFETCH(1);

    for (int s = 0; s < NT; s++) {
        if (s + 1 < NT) { asm volatile("cp.async.wait_group 1;"); }
        else            { asm volatile("cp.async.wait_group 0;"); }
        __syncthreads();
        if (s + 2 < NT) HG_PREFETCH(s + 2);

        const uint32_t buf = smem_u32(smem + (s % 3) * HG_STAGE);
        #pragma unroll
        for (int kk = 0; kk < 4; kk++) {
            uint32_t a[2][4];
            #pragma unroll
            for (int mi = 0; mi < 2; mi++)
                ldsm_x4(a[mi], buf + rowA_off + mi*16*144 + kk*32);
            uint32_t b4[4][4];
            #pragma unroll
            for (int p = 0; p < 4; p++)
                ldsm_x4(b4[p], buf + rowB_off + p*16*144 + kk*32);
            #pragma unroll
            for (int mi = 0; mi < 2; mi++)
                #pragma unroll
                for (int ni = 0; ni < 8; ni++)
                    mma_f16(acc[mi][ni], a[mi], &b4[ni >> 1][(ni & 1)*2]);
        }
    }
    #undef HG_PREFETCH

    if (EPI & 16) {
        // fused per-head L2 normalize: one warp's 64-col tile == one head.
        #pragma unroll
        for (int mi = 0; mi < 2; mi++) {
            const int r0 = bm + wm*32 + mi*16 + (lane>>2);
            float vv[2][16];
            #pragma unroll
            for (int ni = 0; ni < 8; ni++) {
                const int c = bn + wn*64 + ni*8 + 2*(lane & 3);
                const float2 bb = *(const float2*)(bias + c);
                vv[0][2*ni]   = acc[mi][ni][0] + bb.x;
                vv[0][2*ni+1] = acc[mi][ni][1] + bb.y;
                vv[1][2*ni]   = acc[mi][ni][2] + bb.x;
                vv[1][2*ni+1] = acc[mi][ni][3] + bb.y;
            }
            #pragma unroll
            for (int hf = 0; hf < 2; hf++) {
                float ss = 0.f;
                #pragma unroll
                for (int j = 0; j < 16; j++) ss += vv[hf][j] * vv[hf][j];
                ss += __shfl_xor_sync(0xffffffffu, ss, 1);
                ss += __shfl_xor_sync(0xffffffffu, ss, 2);
                const float inv = 1.f / fmaxf(sqrtf(ss), 1e-12f);
                const int r = r0 + hf*8;
                #pragma unroll
                for (int ni = 0; ni < 8; ni++) {
                    const int c = bn + wn*64 + ni*8 + 2*(lane & 3);
                    *(__half2*)((__half*)Cv + (size_t)r * N + c) =
                        __floats2half2_rn(vv[hf][2*ni] * inv, vv[hf][2*ni+1] * inv);
                }
            }
        }
    } else {
        #pragma unroll
        for (int mi = 0; mi < 2; mi++) {
            const int r0 = bm + wm*32 + mi*16 + (lane>>2);
            #pragma unroll
            for (int ni = 0; ni < 8; ni++) {
                const int c = bn + wn*64 + ni*8 + 2*(lane & 3);
                const float2 bb = *(const float2*)(bias + c);
                #pragma unroll
                for (int half_ = 0; half_ < 2; half_++) {
                    const int r = r0 + half_*8;
                    float v0 = acc[mi][ni][2*half_+0] + bb.x;
                    float v1 = acc[mi][ni][2*half_+1] + bb.y;
                    if (EPI & 1) {
                        const float2 rr = *(const float2*)(R + (size_t)r * N + c);
                        v0 += rr.x; v1 += rr.y;
                    }
                    if (EPI & 2) {
                        v0 = 0.5f * v0 * (1.f + erff(v0 * 0.70710678118654752f));
                        v1 = 0.5f * v1 * (1.f + erff(v1 * 0.70710678118654752f));
                    }
                    if (EPI & 8)
                        *(__half2*)((__half*)Cv + (size_t)r * N + c) = __floats2half2_rn(v0, v1);
                    else
                        *(float2*)((float*)Cv + (size_t)r * N + c) = make_float2(v0, v1);
                }
            }
        }
    }
}

// ---------------- V transpose: hv fp16 [b*Lk+t][E] -> vt fp16 [b, E][Lk] ----------------
__global__ void vtrans_kernel(const __half* __restrict__ vp, __half* __restrict__ vt)
{
    const int t0 = blockIdx.x * 32;
    const int d0 = blockIdx.y * 32;
    const int b  = blockIdx.z;
    __shared__ float t[32][33];
    #pragma unroll
    for (int i = 0; i < 32; i += 8)
        t[threadIdx.y + i][threadIdx.x] =
            __half2float(vp[(size_t)(b*LK + t0 + threadIdx.y + i) * EMBED + d0 + threadIdx.x]);
    __syncthreads();
    #pragma unroll
    for (int i = 0; i < 32; i += 8)
        vt[(size_t)(b*EMBED + d0 + threadIdx.y + i) * LK + t0 + threadIdx.x] =
            __float2half(t[threadIdx.x][threadIdx.y + i]);
}

// ---------------- LayerNorm over 768 ----------------
template<bool DUAL>
__global__ void layernorm_kernel(const float* __restrict__ x,
                                 const float* __restrict__ g,
                                 const float* __restrict__ b,
                                 float* __restrict__ y, __half* __restrict__ yh)
{
    const int row = blockIdx.x;
    const float* xr = x + (size_t)row * EMBED;
    const int tid = threadIdx.x;

    float v0 = xr[tid], v1 = xr[tid + 256], v2 = xr[tid + 512];

    __shared__ float red[8];
    float s = v0 + v1 + v2;
    #pragma unroll
    for (int m = 16; m; m >>= 1) s += __shfl_xor_sync(0xffffffffu, s, m);
    if ((tid & 31) == 0) red[tid >> 5] = s;
    __syncthreads();
    s = 0.f;
    #pragma unroll
    for (int w = 0; w < 8; w++) s += red[w];
    const float mu = s * (1.f / EMBED);
    __syncthreads();

    float d0 = v0 - mu, d1 = v1 - mu, d2 = v2 - mu;
    float ss = d0*d0 + d1*d1 + d2*d2;
    #pragma unroll
    for (int m = 16; m; m >>= 1) ss += __shfl_xor_sync(0xffffffffu, ss, m);
    if ((tid & 31) == 0) red[tid >> 5] = ss;
    __syncthreads();
    ss = 0.f;
    #pragma unroll
    for (int w = 0; w < 8; w++) ss += red[w];
    const float inv = rsqrtf(ss * (1.f / EMBED) + 1e-5f);

    float o0 = d0 * inv * g[tid]       + b[tid];
    float o1 = d1 * inv * g[tid + 256] + b[tid + 256];
    float o2 = d2 * inv * g[tid + 512] + b[tid + 512];
    float* yr = y + (size_t)row * EMBED;
    yr[tid] = o0; yr[tid + 256] = o1; yr[tid + 512] = o2;
    if (DUAL) {
        __half* hr = yh + (size_t)row * EMBED;
        hr[tid] = __float2half(o0);
        hr[tid + 256] = __float2half(o1);
        hr[tid + 512] = __float2half(o2);
    }
}

// ---------------- fp16 flash attention: 128-row q-tile, register-resident P ----------------
#define ATT_SMEM ((128*72 + 4*64*72) * 2)   /* 55296 B */

__global__ __launch_bounds__(256, 2)
void attn_kernel(const __half* __restrict__ q, const __half* __restrict__ k,
                 const __half* __restrict__ vt, __half* __restrict__ out, int bofs)
{
    extern __shared__ __half hsm[];
    __half* Qs    = hsm;                            // [128][72]
    __half* Ks[2] = { hsm + 128*72,            hsm + 128*72 + 64*72 };
    __half* Vs[2] = { hsm + 128*72 + 2*64*72,  hsm + 128*72 + 3*64*72 };

    const int tid  = threadIdx.x;
    const int lane = tid & 31;
    const int warp = tid >> 5;
    const int q0 = blockIdx.x * 128;
    const int h  = blockIdx.y;
    const int b  = blockIdx.z + bofs;

    const __half* qb  = q  + ((size_t)(b*LQ + q0)) * EMBED + h * HDIM;
    const __half* kb  = k  + ((size_t)(b*LK))      * EMBED + h * HDIM;
    const __half* vtb = vt + ((size_t)(b*EMBED + h*HDIM)) * LK;

    const int rl = tid >> 3;
    const int cl = (tid & 7) * 8;

    #pragma unroll
    for (int i = 0; i < 4; i++) {
        int r = rl + 32*i;
        cpasync16(Qs + r*72 + cl, qb + (size_t)r * EMBED + cl);
    }
    #pragma unroll
    for (int i = 0; i < 2; i++) {
        int r = rl + 32*i;
        cpasync16(Ks[0] + r*72 + cl, kb  + (size_t)r * EMBED + cl);
        cpasync16(Vs[0] + r*72 + cl, vtb + (size_t)r * LK + cl);
    }
    CP_COMMIT();

    float o[8][4];
    #pragma unroll
    for (int ni = 0; ni < 8; ni++)
        #pragma unroll
        for (int t = 0; t < 4; t++) o[ni][t] = 0.f;
    float l0 = 0.f, l1 = 0.f;

    const int rql = lane >> 2;
    const int g2 = lane >> 3, ri = lane & 7;
    const uint32_t aQoff = (uint32_t)((warp*16 + (g2 & 1)*8 + ri) * 144 + (g2 >> 1)*16);
    const uint32_t bOff  = (uint32_t)(((g2 >> 1)*8 + ri) * 144 + (g2 & 1)*16);
    const uint32_t qA    = smem_u32(Qs) + aQoff;

    uint32_t qf[4][4];

    for (int kt = 0; kt < LK/64; kt++) {
        asm volatile("cp.async.wait_group 0;");
        __syncthreads();

        if (kt == 0) {
            #pragma unroll
            for (int kk = 0; kk < 4; kk++)
                ldsm_x4(qf[kk], qA + kk*32);
        }

        const uint32_t kB = smem_u32(Ks[kt & 1]) + bOff;
        const uint32_t vB = smem_u32(Vs[kt & 1]) + bOff;

        if (kt + 1 < LK/64) {
            __half* ksn = Ks[(kt+1) & 1];
            __half* vsn = Vs[(kt+1) & 1];
            const __half* kp = kb  + (size_t)(kt+1) * 64 * EMBED;
            const __half* vp = vtb + (size_t)(kt+1) * 64;
            #pragma unroll
            for (int i = 0; i < 2; i++) {
                int r = rl + 32*i;
                cpasync16(ksn + r*72 + cl, kp + (size_t)r * EMBED + cl);
                cpasync16(vsn + r*72 + cl, vp + (size_t)r * LK + cl);
            }
            CP_COMMIT();
        }

        float s[8][4];
        #pragma unroll
        for (int ni = 0; ni < 8; ni++)
            #pragma unroll
            for (int t = 0; t < 4; t++) s[ni][t] = 0.f;

        #pragma unroll
        for (int kk = 0; kk < 4; kk++) {
            uint32_t bf4[4][4];
            #pragma unroll
            for (int p = 0; p < 4; p++)
                ldsm_x4(bf4[p], kB + p*16*144 + kk*32);
            #pragma unroll
            for (int ni = 0; ni < 8; ni++)
                mma_f16(s[ni], qf[kk], &bf4[ni >> 1][(ni & 1)*2]);
        }

        uint32_t ph[8][2];
        #pragma unroll
        for (int ni = 0; ni < 8; ni++) {
            float p0 = __expf(s[ni][0] - 1.f);
            float p1 = __expf(s[ni][1] - 1.f);
            float p2 = __expf(s[ni][2] - 1.f);
            float p3 = __expf(s[ni][3] - 1.f);
            l0 += p0 + p1;
            l1 += p2 + p3;
            ph[ni][0] = pack2(p0, p1);
            ph[ni][1] = pack2(p2, p3);
        }

        #pragma unroll
        for (int kk = 0; kk < 4; kk++) {
            uint32_t a[4] = { ph[2*kk][0], ph[2*kk][1], ph[2*kk+1][0], ph[2*kk+1][1] };
            uint32_t bf4[4][4];
            #pragma unroll
            for (int p = 0; p < 4; p++)
                ldsm_x4(bf4[p], vB + p*16*144 + kk*32);
            #pragma unroll
            for (int ni = 0; ni < 8; ni++)
                mma_f16(o[ni], a, &bf4[ni >> 1][(ni & 1)*2]);
        }
    }

    l0 += __shfl_xor_sync(0xffffffffu, l0, 1);
    l0 += __shfl_xor_sync(0xffffffffu, l0, 2);
    l1 += __shfl_xor_sync(0xffffffffu, l1, 1);
    l1 += __shfl_xor_sync(0xffffffffu, l1, 2);
    const float inv0 = 1.f / l0, inv1 = 1.f / l1;

    const int r = b*LQ + q0 + warp*16 + rql;
    #pragma unroll
    for (int ni = 0; ni < 8; ni++) {
        const int c = h*HDIM + ni*8 + 2*(lane & 3);
        *(__half2*)(out + (size_t)r * EMBED + c)     = __floats2half2_rn(o[ni][0]*inv0, o[ni][1]*inv0);
        *(__half2*)(out + (size_t)(r+8) * EMBED + c) = __floats2half2_rn(o[ni][2]*inv1, o[ni][3]*inv1);
    }
}

// ---------------- launch ----------------
extern "C" void kernel_launch(void* const* d_in, const int* in_sizes, int n_in,
                              void* d_out, int out_size)
{
    const float* image_tokens = (const float*)d_in[0];
    const float* point_tokens = (const float*)d_in[1];
    const float* image_pos    = (const float*)d_in[2];
    const float* point_pos    = (const float*)d_in[3];
    const float* Wip = (const float*)d_in[4];   const float* bip = (const float*)d_in[5];
    const float* Wpp = (const float*)d_in[6];   const float* bpp = (const float*)d_in[7];
    const float* Wq  = (const float*)d_in[8];   const float* bq  = (const float*)d_in[9];
    const float* Wk  = (const float*)d_in[10];  const float* bk  = (const float*)d_in[11];
    const float* Wv  = (const float*)d_in[12];  const float* bv  = (const float*)d_in[13];
    const float* Wo  = (const float*)d_in[14];  const float* bo  = (const float*)d_in[15];
    const float* g1  = (const float*)d_in[16];  const float* b1  = (const float*)d_in[17];
    const float* g2  = (const float*)d_in[18];  const float* b2  = (const float*)d_in[19];
    const float* Wf1 = (const float*)d_in[20];  const float* bf1 = (const float*)d_in[21];
    const float* Wf2 = (const float*)d_in[22];  const float* bf2 = (const float*)d_in[23];
    float* out = (float*)d_out;

    float  *op, *ln1p, *f2p;
    __half *hA, *hB, *hv, *hip, *hpp, *hpt, *qh, *kh, *vt, *hat, *hln, *hff, *wh;
    cudaGetSymbolAddress((void**)&op,  g_o);
    cudaGetSymbolAddress((void**)&ln1p,g_ln1);
    cudaGetSymbolAddress((void**)&f2p, g_f2);
    cudaGetSymbolAddress((void**)&hA,  g_hA);
    cudaGetSymbolAddress((void**)&hB,  g_hB);
    cudaGetSymbolAddress((void**)&hv,  g_hv);
    cudaGetSymbolAddress((void**)&hip, g_hip);
    cudaGetSymbolAddress((void**)&hpp, g_hpp);
    cudaGetSymbolAddress((void**)&hpt, g_hpt);
    cudaGetSymbolAddress((void**)&qh,  g_qh);
    cudaGetSymbolAddress((void**)&kh,  g_kh);
    cudaGetSymbolAddress((void**)&vt,  g_vt);
    cudaGetSymbolAddress((void**)&hat, g_hat);
    cudaGetSymbolAddress((void**)&hln, g_hln);
    cudaGetSymbolAddress((void**)&hff, g_hff);
    cudaGetSymbolAddress((void**)&wh,  g_wh);

    __half* WipT = wh + 0*WSZ;
    __half* WppT = wh + 1*WSZ;
    __half* WqT  = wh + 2*WSZ;
    __half* WkT  = wh + 3*WSZ;
    __half* WvT  = wh + 4*WSZ;
    __half* WoT  = wh + 5*WSZ;
    __half* Wf1T = wh + 6*WSZ;
    __half* Wf2T = wh + 6*WSZ + WFSZ;

    static cudaStream_t s1 = nullptr, s2 = nullptr;
    static cudaEvent_t evA = nullptr, evK = nullptr, evV = nullptr, evJ = nullptr, evT = nullptr;
    if (!s1) {
        cudaStreamCreateWithFlags(&s1, cudaStreamNonBlocking);
        cudaStreamCreateWithFlags(&s2, cudaStreamNonBlocking);
        cudaEventCreateWithFlags(&evA, cudaEventDisableTiming);
        cudaEventCreateWithFlags(&evK, cudaEventDisableTiming);
        cudaEventCreateWithFlags(&evV, cudaEventDisableTiming);
        cudaEventCreateWithFlags(&evJ, cudaEventDisableTiming);
        cudaEventCreateWithFlags(&evT, cudaEventDisableTiming);
    }

    cudaFuncSetAttribute(hgemm<1>,  cudaFuncAttributeMaxDynamicSharedMemorySize, HG_SMEM);
    cudaFuncSetAttribute(hgemm<8>,  cudaFuncAttributeMaxDynamicSharedMemorySize, HG_SMEM);
    cudaFuncSetAttribute(hgemm<9>,  cudaFuncAttributeMaxDynamicSharedMemorySize, HG_SMEM);
    cudaFuncSetAttribute(hgemm<10>, cudaFuncAttributeMaxDynamicSharedMemorySize, HG_SMEM);
    cudaFuncSetAttribute(hgemm<16>, cudaFuncAttributeMaxDynamicSharedMemorySize, HG_SMEM);
    cudaFuncSetAttribute(attn_kernel, cudaFuncAttributeMaxDynamicSharedMemorySize, ATT_SMEM);

    // prep (origin stream), then fork via evA
    WPtrs P;
    P.s[0]=Wip; P.s[1]=Wpp; P.s[2]=Wq; P.s[3]=Wk; P.s[4]=Wv; P.s[5]=Wo; P.s[6]=Wf1; P.s[7]=Wf2;
    twr_all<<<dim3(48, 48, 8), dim3(32, 8)>>>(P, wh);
    cvt3<<<(MQ*EMBED/4 + 255)/256, 256>>>(image_pos, point_pos, point_tokens, hip, hpp, hpt);
    cudaEventRecord(evA, 0);

    // branch Q (s0)
    hgemm<9><<<dim3(EMBED/128, MQ/128), 256, HG_SMEM>>>(hip, WipT, bip, image_tokens, hA, MQ, EMBED, EMBED);
    hgemm<16><<<dim3(EMBED/128, MQ/128), 256, HG_SMEM>>>(hA, WqT, bq, nullptr, qh, MQ, EMBED, EMBED);

    // branch K (s1)
    cudaStreamWaitEvent(s1, evA, 0);
    hgemm<9><<<dim3(EMBED/128, MK/128), 256, HG_SMEM, s1>>>(hpp, WppT, bpp, point_tokens, hB, MK, EMBED, EMBED);
    hgemm<16><<<dim3(EMBED/128, MK/128), 256, HG_SMEM, s1>>>(hB, WkT, bk, nullptr, kh, MK, EMBED, EMBED);
    cudaEventRecord(evK, s1);

    // branch V (s2)
    cudaStreamWaitEvent(s2, evA, 0);
    hgemm<8><<<dim3(EMBED/128, MK/128), 256, HG_SMEM, s2>>>(hpt, WvT, bv, nullptr, hv, MK, EMBED, EMBED);
    vtrans_kernel<<<dim3(LK/32, EMBED/32, BATCH), dim3(32, 8), 0, s2>>>(hv, vt);
    cudaEventRecord(evV, s2);

    // join on s0; evJ marks "q,k,v all ready"
    cudaStreamWaitEvent(0, evK, 0);
    cudaStreamWaitEvent(0, evV, 0);
    cudaEventRecord(evJ, 0);

    // -------- chunk 0 (batches 0-1, rows 0..4095) on s0 --------
    attn_kernel<<<dim3(LQ/128, HEADS, 2), 256, ATT_SMEM>>>(qh, kh, vt, hat, 0);
    hgemm<1><<<dim3(EMBED/128, MH/128), 256, HG_SMEM>>>(hat, WoT, bo, image_tokens, op, MH, EMBED, EMBED);
    layernorm_kernel<true><<<MH, 256>>>(op, g1, b1, ln1p, hln);
    hgemm<10><<<dim3(FF/128, MH/128), 256, HG_SMEM>>>(hln, Wf1T, bf1, nullptr, hff, MH, FF, EMBED);
    hgemm<1><<<dim3(EMBED/128, MH/128), 256, HG_SMEM>>>(hff, Wf2T, bf2, ln1p, f2p, MH, EMBED, FF);
    layernorm_kernel<false><<<MH, 256>>>(f2p, g2, b2, out, nullptr);

    // -------- chunk 1 (batches 2-3, rows 4096..8191) on s1 --------
    const size_t rE = (size_t)MH * EMBED;
    const size_t rF = (size_t)MH * FF;
    cudaStreamWaitEvent(s1, evJ, 0);
    attn_kernel<<<dim3(LQ/128, HEADS, 2), 256, ATT_SMEM, s1>>>(qh, kh, vt, hat, 2);
    hgemm<1><<<dim3(EMBED/128, MH/128), 256, HG_SMEM, s1>>>(hat + rE, WoT, bo, image_tokens + rE, op + rE, MH, EMBED, EMBED);
    layernorm_kernel<true><<<MH, 256, 0, s1>>>(op + rE, g1, b1, ln1p + rE, hln + rE);
    hgemm<10><<<dim3(FF/128, MH/128), 256, HG_SMEM, s1>>>(hln + rE, Wf1T, bf1, nullptr, hff + rF, MH, FF, EMBED);
    hgemm<1><<<dim3(EMBED/128, MH/128), 256, HG_SMEM, s1>>>(hff + rF, Wf2T, bf2, ln1p + rE, f2p + rE, MH, EMBED, FF);
    layernorm_kernel<false><<<MH, 256, 0, s1>>>(f2p + rE, g2, b2, out + rE, nullptr);
    cudaEventRecord(evT, s1);

    // join all side work back into origin stream before capture ends
    cudaStreamWaitEvent(0, evT, 0);
}